// round 1
// baseline (speedup 1.0000x reference)
#include <cuda_runtime.h>
#include <math.h>

#define BB 32
#define NN 540
#define DD 512
#define HH 8
#define DHE 64
#define HB (HH*BB)          // 256
#define BN (BB*NN)          // 17280
#define PCLIP 539

// -------- scratch (device globals; no allocations allowed) --------
__device__ float g_q[(size_t)HB*NN*DHE];
__device__ float g_k[(size_t)HB*NN*DHE];
__device__ float g_v[(size_t)HB*NN*DHE];
__device__ float g_s[(size_t)HB*NN*NN];    // scores, then attn in-place
__device__ float g_ao[(size_t)HB*NN*DHE];  // attn @ v, head-major
__device__ float g_o[(size_t)BN*DD];       // pre-LN (proj + residual)

// ============================================================
// K1: QKV projection GEMM  Y = X @ W + b, scattered head-major.
// M=17280, N=512, K=512.  64x64 tile, TK=16, 256 threads, 4x4/thread.
// ============================================================
__global__ void qkv_gemm(const float* __restrict__ X,
                         const float* __restrict__ W,
                         const float* __restrict__ bias,
                         int which)
{
    __shared__ float As[16][65];   // [k][m], padded
    __shared__ float Bs[16][64];   // [k][n]

    const int tx = threadIdx.x, ty = threadIdx.y;
    const int tid = ty * 16 + tx;
    const int m0 = blockIdx.x * 64;
    const int n0 = blockIdx.y * 64;

    float acc[4][4] = {};

    for (int k0 = 0; k0 < DD; k0 += 16) {
        #pragma unroll
        for (int i = tid; i < 1024; i += 256) {
            int r = i >> 4, c = i & 15;
            As[c][r] = X[(size_t)(m0 + r) * DD + k0 + c];
        }
        #pragma unroll
        for (int i = tid; i < 1024; i += 256) {
            int c = i >> 6, j = i & 63;
            Bs[c][j] = W[(size_t)(k0 + c) * DD + n0 + j];
        }
        __syncthreads();
        #pragma unroll
        for (int kk = 0; kk < 16; kk++) {
            float a[4], bv[4];
            #pragma unroll
            for (int ii = 0; ii < 4; ii++) a[ii] = As[kk][ty * 4 + ii];
            #pragma unroll
            for (int jj = 0; jj < 4; jj++) bv[jj] = Bs[kk][tx * 4 + jj];
            #pragma unroll
            for (int ii = 0; ii < 4; ii++)
                #pragma unroll
                for (int jj = 0; jj < 4; jj++)
                    acc[ii][jj] = fmaf(a[ii], bv[jj], acc[ii][jj]);
        }
        __syncthreads();
    }

    float* out = (which == 0) ? g_q : (which == 1) ? g_k : g_v;
    #pragma unroll
    for (int ii = 0; ii < 4; ii++) {
        int m = m0 + ty * 4 + ii;
        int b = m / NN, n = m % NN;
        #pragma unroll
        for (int jj = 0; jj < 4; jj++) {
            int e = n0 + tx * 4 + jj;
            int h = e >> 6, dh = e & 63;
            out[((size_t)(h * BB + b) * NN + n) * DHE + dh] = acc[ii][jj] + bias[e];
        }
    }
}

// ============================================================
// K2: scores  S[x,i,j] = 0.125 * dot(q_i, k_j + pos_k[clip(j-i)+539])
// 32x32 tile per block; skip tiles entirely beyond valid_len.
// ============================================================
__global__ void scores_kernel(const float* __restrict__ pos_k,
                              const int* __restrict__ vl)
{
    __shared__ float qs[32][65];
    __shared__ float ks[32][65];
    __shared__ float ps[63][65];

    const int x = blockIdx.z;
    const int b = x & (BB - 1);
    const int vlen = vl[b];
    const int j0 = blockIdx.x * 32;
    const int i0 = blockIdx.y * 32;
    if (j0 >= vlen) return;   // softmax writes zeros there; never read

    const int tx = threadIdx.x, ty = threadIdx.y;
    const int tid = ty * 32 + tx;
    const float* qb = g_q + (size_t)x * NN * DHE;
    const float* kb = g_k + (size_t)x * NN * DHE;

    #pragma unroll
    for (int i = tid; i < 2048; i += 256) {
        int r = i >> 6, d = i & 63;
        qs[r][d] = (i0 + r < NN) ? qb[(size_t)(i0 + r) * DHE + d] : 0.f;
        ks[r][d] = (j0 + r < NN) ? kb[(size_t)(j0 + r) * DHE + d] : 0.f;
    }
    for (int i = tid; i < 63 * 64; i += 256) {
        int rr = i >> 6, d = i & 63;
        int rel = j0 - i0 + rr - 31;
        rel = min(max(rel, -PCLIP), PCLIP);
        ps[rr][d] = pos_k[(size_t)(rel + PCLIP) * DHE + d];
    }
    __syncthreads();

    float acc[4] = {0.f, 0.f, 0.f, 0.f};
    #pragma unroll
    for (int d = 0; d < 64; d++) {
        float kv = ks[tx][d];
        #pragma unroll
        for (int ii = 0; ii < 4; ii++) {
            int ti = ty + 8 * ii;
            acc[ii] = fmaf(qs[ti][d], kv + ps[tx - ti + 31][d], acc[ii]);
        }
    }

    float* srow = g_s + (size_t)x * NN * NN;
    #pragma unroll
    for (int ii = 0; ii < 4; ii++) {
        int i = i0 + ty + 8 * ii;
        int j = j0 + tx;
        if (i < NN && j < NN)
            srow[(size_t)i * NN + j] = acc[ii] * 0.125f;
    }
}

// ============================================================
// K3: masked softmax over last axis (in-place in g_s).
// Only j < valid_len participates; j >= valid_len written as 0.
// ============================================================
__global__ void softmax_kernel(const int* __restrict__ vl)
{
    const int x = blockIdx.y;
    const int i = blockIdx.x;
    const int b = x & (BB - 1);
    const int vlen = vl[b];
    float* row = g_s + ((size_t)x * NN + i) * NN;
    const int tid = threadIdx.x;  // 256

    __shared__ float red[8];

    float v[3];
    float m = -1e30f;
    #pragma unroll
    for (int t = 0; t < 3; t++) {
        int j = tid + t * 256;
        v[t] = (j < vlen) ? row[j] : -1e30f;
        m = fmaxf(m, v[t]);
    }
    #pragma unroll
    for (int off = 16; off > 0; off >>= 1)
        m = fmaxf(m, __shfl_xor_sync(0xffffffff, m, off));
    if ((tid & 31) == 0) red[tid >> 5] = m;
    __syncthreads();
    float bm = red[0];
    #pragma unroll
    for (int w = 1; w < 8; w++) bm = fmaxf(bm, red[w]);

    float s = 0.f;
    #pragma unroll
    for (int t = 0; t < 3; t++) {
        int j = tid + t * 256;
        if (j < vlen) { v[t] = expf(v[t] - bm); s += v[t]; }
        else v[t] = 0.f;
    }
    #pragma unroll
    for (int off = 16; off > 0; off >>= 1)
        s += __shfl_xor_sync(0xffffffff, s, off);
    __syncthreads();  // done reading red (max phase)
    if ((tid & 31) == 0) red[tid >> 5] = s;
    __syncthreads();
    float tot = red[0];
    #pragma unroll
    for (int w = 1; w < 8; w++) tot += red[w];
    float inv = 1.f / tot;

    #pragma unroll
    for (int t = 0; t < 3; t++) {
        int j = tid + t * 256;
        if (j < NN) row[j] = v[t] * inv;
    }
}

// ============================================================
// K4: out = attn @ v   per x: [540,540]@[540,64]; K truncated at valid_len.
// block: 32 rows x 64 cols, blockDim(64,4).
// ============================================================
__global__ void av_kernel(const int* __restrict__ vl)
{
    __shared__ float as[32][33];
    __shared__ float vs[32][64];

    const int x = blockIdx.y;
    const int b = x & (BB - 1);
    const int vlen = vl[b];
    const int i0 = blockIdx.x * 32;
    const int tx = threadIdx.x;   // 0..63 (dh)
    const int ty = threadIdx.y;   // 0..3
    const int tid = ty * 64 + tx;

    const float* attn = g_s + (size_t)x * NN * NN;
    const float* vb = g_v + (size_t)x * NN * DHE;

    float acc[8] = {};
    const int ktiles = (vlen + 31) / 32;
    for (int kt = 0; kt < ktiles; kt++) {
        int k0 = kt * 32;
        #pragma unroll
        for (int i = tid; i < 1024; i += 256) {
            int r = i >> 5, c = i & 31;
            as[r][c] = (i0 + r < NN && k0 + c < NN)
                       ? attn[(size_t)(i0 + r) * NN + k0 + c] : 0.f;
        }
        #pragma unroll
        for (int i = tid; i < 2048; i += 256) {
            int r = i >> 6, c = i & 63;
            vs[r][c] = (k0 + r < NN) ? vb[(size_t)(k0 + r) * DHE + c] : 0.f;
        }
        __syncthreads();
        #pragma unroll
        for (int kk = 0; kk < 32; kk++) {
            float vv = vs[kk][tx];
            #pragma unroll
            for (int r = 0; r < 8; r++)
                acc[r] = fmaf(as[r * 4 + ty][kk], vv, acc[r]);
        }
        __syncthreads();
    }

    float* ob = g_ao + (size_t)x * NN * DHE;
    #pragma unroll
    for (int r = 0; r < 8; r++) {
        int i = i0 + r * 4 + ty;
        if (i < NN) ob[(size_t)i * DHE + tx] = acc[r];
    }
}

// ============================================================
// K5: output projection  o = merge_heads(ao) @ Wh + bh + residual(query)
// Same tiling as K1, A gathered head-major.
// ============================================================
__global__ void outproj_gemm(const float* __restrict__ W,
                             const float* __restrict__ bias,
                             const float* __restrict__ query)
{
    __shared__ float As[16][65];
    __shared__ float Bs[16][64];

    const int tx = threadIdx.x, ty = threadIdx.y;
    const int tid = ty * 16 + tx;
    const int m0 = blockIdx.x * 64;
    const int n0 = blockIdx.y * 64;

    float acc[4][4] = {};

    for (int k0 = 0; k0 < DD; k0 += 16) {
        const int h = k0 >> 6;
        const int dhb = k0 & 63;
        #pragma unroll
        for (int i = tid; i < 1024; i += 256) {
            int r = i >> 4, c = i & 15;
            int m = m0 + r;
            int b = m / NN, n = m % NN;
            As[c][r] = g_ao[((size_t)(h * BB + b) * NN + n) * DHE + dhb + c];
        }
        #pragma unroll
        for (int i = tid; i < 1024; i += 256) {
            int c = i >> 6, j = i & 63;
            Bs[c][j] = W[(size_t)(k0 + c) * DD + n0 + j];
        }
        __syncthreads();
        #pragma unroll
        for (int kk = 0; kk < 16; kk++) {
            float a[4], bv[4];
            #pragma unroll
            for (int ii = 0; ii < 4; ii++) a[ii] = As[kk][ty * 4 + ii];
            #pragma unroll
            for (int jj = 0; jj < 4; jj++) bv[jj] = Bs[kk][tx * 4 + jj];
            #pragma unroll
            for (int ii = 0; ii < 4; ii++)
                #pragma unroll
                for (int jj = 0; jj < 4; jj++)
                    acc[ii][jj] = fmaf(a[ii], bv[jj], acc[ii][jj]);
        }
        __syncthreads();
    }

    #pragma unroll
    for (int ii = 0; ii < 4; ii++) {
        int m = m0 + ty * 4 + ii;
        #pragma unroll
        for (int jj = 0; jj < 4; jj++) {
            int e = n0 + tx * 4 + jj;
            g_o[(size_t)m * DD + e] = acc[ii][jj] + bias[e] + query[(size_t)m * DD + e];
        }
    }
}

// ============================================================
// K6: LayerNorm over D=512 per row -> d_out
// ============================================================
__global__ void ln_kernel(const float* __restrict__ gamma,
                          const float* __restrict__ beta,
                          float* __restrict__ out)
{
    const int m = blockIdx.x;
    const float* xr = g_o + (size_t)m * DD;
    const int tid = threadIdx.x;  // 256

    __shared__ float red[8];

    float x0 = xr[tid], x1 = xr[tid + 256];
    float s = x0 + x1;
    #pragma unroll
    for (int off = 16; off > 0; off >>= 1)
        s += __shfl_xor_sync(0xffffffff, s, off);
    if ((tid & 31) == 0) red[tid >> 5] = s;
    __syncthreads();
    float tot = 0.f;
    #pragma unroll
    for (int w = 0; w < 8; w++) tot += red[w];
    float mean = tot * (1.f / DD);

    float d0 = x0 - mean, d1 = x1 - mean;
    float ss = d0 * d0 + d1 * d1;
    #pragma unroll
    for (int off = 16; off > 0; off >>= 1)
        ss += __shfl_xor_sync(0xffffffff, ss, off);
    __syncthreads();
    if ((tid & 31) == 0) red[tid >> 5] = ss;
    __syncthreads();
    float tss = 0.f;
    #pragma unroll
    for (int w = 0; w < 8; w++) tss += red[w];
    float var = tss * (1.f / DD);
    float rstd = rsqrtf(var + 1e-7f);

    out[(size_t)m * DD + tid]       = gamma[tid]       * d0 * rstd + beta[tid];
    out[(size_t)m * DD + tid + 256] = gamma[tid + 256] * d1 * rstd + beta[tid + 256];
}

// ============================================================
extern "C" void kernel_launch(void* const* d_in, const int* in_sizes, int n_in,
                              void* d_out, int out_size)
{
    const float* query = (const float*)d_in[0];
    const float* Wq    = (const float*)d_in[1];
    const float* bq    = (const float*)d_in[2];
    const float* Wk    = (const float*)d_in[3];
    const float* bk    = (const float*)d_in[4];
    const float* Wv    = (const float*)d_in[5];
    const float* bv    = (const float*)d_in[6];
    const float* Wh    = (const float*)d_in[7];
    const float* bh    = (const float*)d_in[8];
    const float* pos_k = (const float*)d_in[9];
    const float* gamma = (const float*)d_in[10];
    const float* beta  = (const float*)d_in[11];
    const int*   vl    = (const int*)d_in[12];
    float* out = (float*)d_out;

    dim3 gb(BN / 64, DD / 64);   // 270 x 8
    dim3 tb(16, 16);
    qkv_gemm<<<gb, tb>>>(query, Wq, bq, 0);
    qkv_gemm<<<gb, tb>>>(query, Wk, bk, 1);
    qkv_gemm<<<gb, tb>>>(query, Wv, bv, 2);

    scores_kernel<<<dim3(17, 17, HB), dim3(32, 8)>>>(pos_k, vl);
    softmax_kernel<<<dim3(NN, HB), 256>>>(vl);
    av_kernel<<<dim3(17, HB), dim3(64, 4)>>>(vl);

    outproj_gemm<<<gb, tb>>>(Wh, bh, query);
    ln_kernel<<<BN, 256>>>(gamma, beta, out);
}

// round 2
// speedup vs baseline: 1.5358x; 1.5358x over previous
#include <cuda_runtime.h>
#include <cstdint>
#include <math.h>

#define BB 32
#define NN 540
#define DD 512
#define HH 8
#define DHE 64
#define HB (HH*BB)          // 256
#define BN (BB*NN)          // 17280
#define PCLIP 539
#define RLEN (2*PCLIP+1)    // 1079

// -------- scratch (device globals) --------
// g_q/g_k/g_v/g_ao hold tf32-bit-pattern floats (consumed only by mma).
__device__ float g_q[(size_t)HB*NN*DHE];
__device__ float g_k[(size_t)HB*NN*DHE];
__device__ float g_v[(size_t)HB*NN*DHE];
__device__ float g_s[(size_t)HB*NN*NN];    // scores fp32, then attn (tf32 bits) in-place
__device__ float g_ao[(size_t)HB*NN*DHE];
__device__ float g_o[(size_t)BN*DD];

// -------- helpers --------
__device__ __forceinline__ uint32_t f2tf(float f) {
    uint32_t u;
    asm("cvt.rna.tf32.f32 %0, %1;" : "=r"(u) : "f"(f));
    return u;
}

__device__ __forceinline__ void mma_tf32(float c[4],
                                         uint32_t a0, uint32_t a1, uint32_t a2, uint32_t a3,
                                         uint32_t b0, uint32_t b1) {
    asm volatile(
        "mma.sync.aligned.m16n8k8.row.col.f32.tf32.tf32.f32 "
        "{%0,%1,%2,%3}, {%4,%5,%6,%7}, {%8,%9}, {%0,%1,%2,%3};\n"
        : "+f"(c[0]), "+f"(c[1]), "+f"(c[2]), "+f"(c[3])
        : "r"(a0), "r"(a1), "r"(a2), "r"(a3), "r"(b0), "r"(b1));
}

// ============================================================
// K1: fused QKV projection, tf32 mma. Block tile 128x64, 8 warps (4m x 2n),
// warp tile 32x32. Shares the X tile across all 3 weights.
// q is pre-scaled by 0.125; outputs stored as tf32 bits, head-major.
// ============================================================
__global__ __launch_bounds__(256) void qkv_fused(const float* __restrict__ X,
                                                 const float* __restrict__ Wq, const float* __restrict__ bq,
                                                 const float* __restrict__ Wk, const float* __restrict__ bk,
                                                 const float* __restrict__ Wv, const float* __restrict__ bv)
{
    __shared__ uint32_t Xs[128][20];
    __shared__ uint32_t Bs[3][16][68];

    const int tid = threadIdx.x;
    const int lane = tid & 31, warp = tid >> 5;
    const int g = lane >> 2, t = lane & 3;
    const int wm = warp >> 1, wn = warp & 1;
    const int m0 = blockIdx.x * 128;
    const int n0 = blockIdx.y * 64;

    const float* Ws[3] = {Wq, Wk, Wv};

    float acc[3][2][4][4];
    #pragma unroll
    for (int w = 0; w < 3; w++)
        #pragma unroll
        for (int am = 0; am < 2; am++)
            #pragma unroll
            for (int an = 0; an < 4; an++)
                #pragma unroll
                for (int e = 0; e < 4; e++) acc[w][am][an][e] = 0.f;

    for (int k0 = 0; k0 < DD; k0 += 16) {
        #pragma unroll
        for (int it = 0; it < 8; it++) {
            int idx = tid + it * 256;
            int r = idx >> 4, c = idx & 15;
            Xs[r][c] = f2tf(X[(size_t)(m0 + r) * DD + k0 + c]);
        }
        #pragma unroll
        for (int w = 0; w < 3; w++) {
            const float* W = Ws[w];
            #pragma unroll
            for (int it = 0; it < 4; it++) {
                int idx = tid + it * 256;
                int kr = idx >> 6, c = idx & 63;
                Bs[w][kr][c] = f2tf(W[(size_t)(k0 + kr) * DD + n0 + c]);
            }
        }
        __syncthreads();

        #pragma unroll
        for (int ks = 0; ks < 16; ks += 8) {
            uint32_t a[2][4];
            #pragma unroll
            for (int am = 0; am < 2; am++) {
                int row = wm * 32 + am * 16;
                a[am][0] = Xs[row + g][ks + t];
                a[am][1] = Xs[row + 8 + g][ks + t];
                a[am][2] = Xs[row + g][ks + t + 4];
                a[am][3] = Xs[row + 8 + g][ks + t + 4];
            }
            #pragma unroll
            for (int w = 0; w < 3; w++) {
                #pragma unroll
                for (int an = 0; an < 4; an++) {
                    int n = wn * 32 + an * 8 + g;
                    uint32_t b0 = Bs[w][ks + t][n];
                    uint32_t b1 = Bs[w][ks + t + 4][n];
                    mma_tf32(acc[w][0][an], a[0][0], a[0][1], a[0][2], a[0][3], b0, b1);
                    mma_tf32(acc[w][1][an], a[1][0], a[1][1], a[1][2], a[1][3], b0, b1);
                }
            }
        }
        __syncthreads();
    }

    // precompute row scatter info: 4 distinct m rows per thread
    int mb[2][2], mn[2][2];
    #pragma unroll
    for (int am = 0; am < 2; am++)
        #pragma unroll
        for (int hl = 0; hl < 2; hl++) {
            int m = m0 + wm * 32 + am * 16 + g + hl * 8;
            mb[am][hl] = m / NN;
            mn[am][hl] = m % NN;
        }

    const float* biases[3] = {bq, bk, bv};
    #pragma unroll
    for (int w = 0; w < 3; w++) {
        float* out = (w == 0) ? g_q : (w == 1) ? g_k : g_v;
        const float* bias = biases[w];
        float scl = (w == 0) ? 0.125f : 1.0f;
        #pragma unroll
        for (int an = 0; an < 4; an++) {
            int col = n0 + wn * 32 + an * 8 + 2 * t;
            #pragma unroll
            for (int cc = 0; cc < 2; cc++) {
                int e = col + cc;
                int h = e >> 6, dh = e & 63;
                float bv_ = bias[e];
                #pragma unroll
                for (int am = 0; am < 2; am++)
                    #pragma unroll
                    for (int hl = 0; hl < 2; hl++) {
                        float val = (acc[w][am][an][hl * 2 + cc] + bv_) * scl;
                        out[((size_t)(h * BB + mb[am][hl]) * NN + mn[am][hl]) * DHE + dh]
                            = __uint_as_float(f2tf(val));
                    }
            }
        }
    }
}

// ============================================================
// K2a: QK batched GEMM (per x), writes g_s = q·k^T (q pre-scaled).
// 64x64 tile, K=64 fully staged. Skips tiles with j0 >= valid_len.
// ============================================================
__global__ __launch_bounds__(256) void qk_kernel(const int* __restrict__ vl)
{
    __shared__ uint32_t qs[64][68];
    __shared__ uint32_t ks[64][68];

    const int x = blockIdx.z;
    const int b = x & (BB - 1);
    const int vlen = vl[b];
    const int j0 = blockIdx.x * 64;
    if (j0 >= vlen) return;
    const int i0 = blockIdx.y * 64;

    const int tid = threadIdx.x;
    const int lane = tid & 31, warp = tid >> 5;
    const int g = lane >> 2, t = lane & 3;
    const int wm = warp >> 1, wn = warp & 1;

    const float* qb = g_q + (size_t)x * NN * DHE;
    const float* kb = g_k + (size_t)x * NN * DHE;

    #pragma unroll
    for (int it = 0; it < 16; it++) {
        int idx = tid + it * 256;
        int r = idx >> 6, c = idx & 63;
        qs[r][c] = (i0 + r < NN) ? __float_as_uint(qb[(size_t)(i0 + r) * DHE + c]) : 0u;
        ks[r][c] = (j0 + r < NN) ? __float_as_uint(kb[(size_t)(j0 + r) * DHE + c]) : 0u;
    }
    __syncthreads();

    float acc[4][4];
    #pragma unroll
    for (int an = 0; an < 4; an++)
        #pragma unroll
        for (int e = 0; e < 4; e++) acc[an][e] = 0.f;

    const int ib = wm * 16;
    #pragma unroll
    for (int kk = 0; kk < 64; kk += 8) {
        uint32_t a0 = qs[ib + g][kk + t];
        uint32_t a1 = qs[ib + 8 + g][kk + t];
        uint32_t a2 = qs[ib + g][kk + t + 4];
        uint32_t a3 = qs[ib + 8 + g][kk + t + 4];
        #pragma unroll
        for (int an = 0; an < 4; an++) {
            int n = wn * 32 + an * 8 + g;
            uint32_t b0 = ks[n][kk + t];
            uint32_t b1 = ks[n][kk + t + 4];
            mma_tf32(acc[an], a0, a1, a2, a3, b0, b1);
        }
    }

    float* srow = g_s + (size_t)x * NN * NN;
    #pragma unroll
    for (int an = 0; an < 4; an++) {
        int j = j0 + wn * 32 + an * 8 + 2 * t;
        #pragma unroll
        for (int hl = 0; hl < 2; hl++) {
            int i = i0 + ib + g + hl * 8;
            if (i < NN) {
                if (j < NN)     srow[(size_t)i * NN + j]     = acc[an][hl * 2 + 0];
                if (j + 1 < NN) srow[(size_t)i * NN + j + 1] = acc[an][hl * 2 + 1];
            }
        }
    }
}

// ============================================================
// K2b: QR banded GEMM: T[x,i,r] = q_i · pos_k[r], scatter-add
// into g_s[x][i][j] at j = r + i - 539 (clip never binds since N-1 == PCLIP).
// ============================================================
__global__ __launch_bounds__(256) void qr_kernel(const float* __restrict__ pos_k,
                                                 const int* __restrict__ vl)
{
    __shared__ uint32_t qs[64][68];
    __shared__ uint32_t ps[64][68];

    const int x = blockIdx.z;
    const int b = x & (BB - 1);
    const int vlen = vl[b];
    const int r0 = blockIdx.x * 64;
    const int i0 = blockIdx.y * 64;
    // band check: j = r + i - 539 over tile
    if (r0 + i0 + 126 - PCLIP < 0) return;
    if (r0 + i0 - PCLIP >= vlen) return;

    const int tid = threadIdx.x;
    const int lane = tid & 31, warp = tid >> 5;
    const int g = lane >> 2, t = lane & 3;
    const int wm = warp >> 1, wn = warp & 1;

    const float* qb = g_q + (size_t)x * NN * DHE;

    #pragma unroll
    for (int it = 0; it < 16; it++) {
        int idx = tid + it * 256;
        int r = idx >> 6, c = idx & 63;
        qs[r][c] = (i0 + r < NN) ? __float_as_uint(qb[(size_t)(i0 + r) * DHE + c]) : 0u;
        ps[r][c] = (r0 + r < RLEN) ? f2tf(pos_k[(size_t)(r0 + r) * DHE + c]) : 0u;
    }
    __syncthreads();

    float acc[4][4];
    #pragma unroll
    for (int an = 0; an < 4; an++)
        #pragma unroll
        for (int e = 0; e < 4; e++) acc[an][e] = 0.f;

    const int ib = wm * 16;
    #pragma unroll
    for (int kk = 0; kk < 64; kk += 8) {
        uint32_t a0 = qs[ib + g][kk + t];
        uint32_t a1 = qs[ib + 8 + g][kk + t];
        uint32_t a2 = qs[ib + g][kk + t + 4];
        uint32_t a3 = qs[ib + 8 + g][kk + t + 4];
        #pragma unroll
        for (int an = 0; an < 4; an++) {
            int n = wn * 32 + an * 8 + g;
            uint32_t b0 = ps[n][kk + t];
            uint32_t b1 = ps[n][kk + t + 4];
            mma_tf32(acc[an], a0, a1, a2, a3, b0, b1);
        }
    }

    float* srow = g_s + (size_t)x * NN * NN;
    #pragma unroll
    for (int an = 0; an < 4; an++) {
        int rr = r0 + wn * 32 + an * 8 + 2 * t;
        #pragma unroll
        for (int hl = 0; hl < 2; hl++) {
            int i = i0 + ib + g + hl * 8;
            if (i < NN) {
                #pragma unroll
                for (int cc = 0; cc < 2; cc++) {
                    int j = rr + cc + i - PCLIP;
                    if (j >= 0 && j < vlen)
                        srow[(size_t)i * NN + j] += acc[an][hl * 2 + cc];
                }
            }
        }
    }
}

// ============================================================
// K3: masked softmax (in-place). Reads fp32 scores for j < vlen,
// writes tf32-bit attn for j < vlen only (tail never read by AV).
// ============================================================
__global__ __launch_bounds__(256) void softmax_kernel(const int* __restrict__ vl)
{
    const int x = blockIdx.y;
    const int i = blockIdx.x;
    const int b = x & (BB - 1);
    const int vlen = vl[b];
    float* row = g_s + ((size_t)x * NN + i) * NN;
    const int tid = threadIdx.x;

    __shared__ float red[8];

    float v[3];
    float m = -1e30f;
    #pragma unroll
    for (int tt = 0; tt < 3; tt++) {
        int j = tid + tt * 256;
        v[tt] = (j < vlen) ? row[j] : -1e30f;
        m = fmaxf(m, v[tt]);
    }
    #pragma unroll
    for (int off = 16; off > 0; off >>= 1)
        m = fmaxf(m, __shfl_xor_sync(0xffffffff, m, off));
    if ((tid & 31) == 0) red[tid >> 5] = m;
    __syncthreads();
    float bm = red[0];
    #pragma unroll
    for (int w = 1; w < 8; w++) bm = fmaxf(bm, red[w]);

    float s = 0.f;
    #pragma unroll
    for (int tt = 0; tt < 3; tt++) {
        int j = tid + tt * 256;
        if (j < vlen) { v[tt] = expf(v[tt] - bm); s += v[tt]; }
        else v[tt] = 0.f;
    }
    #pragma unroll
    for (int off = 16; off > 0; off >>= 1)
        s += __shfl_xor_sync(0xffffffff, s, off);
    __syncthreads();
    if ((tid & 31) == 0) red[tid >> 5] = s;
    __syncthreads();
    float tot = red[0];
    #pragma unroll
    for (int w = 1; w < 8; w++) tot += red[w];
    float inv = 1.f / tot;

    #pragma unroll
    for (int tt = 0; tt < 3; tt++) {
        int j = tid + tt * 256;
        if (j < vlen) row[j] = __uint_as_float(f2tf(v[tt] * inv));
    }
}

// ============================================================
// K4: AV batched GEMM (tf32), K truncated at valid_len.
// C tile 64(i) x 64(dh), K panels of 64.
// ============================================================
__global__ __launch_bounds__(256) void av_kernel(const int* __restrict__ vl)
{
    __shared__ uint32_t as_s[64][68];
    __shared__ uint32_t vs_s[64][68];

    const int x = blockIdx.y;
    const int b = x & (BB - 1);
    const int vlen = vl[b];
    const int i0 = blockIdx.x * 64;

    const int tid = threadIdx.x;
    const int lane = tid & 31, warp = tid >> 5;
    const int g = lane >> 2, t = lane & 3;
    const int wm = warp >> 1, wn = warp & 1;

    const float* attn = g_s + (size_t)x * NN * NN;
    const float* vb = g_v + (size_t)x * NN * DHE;

    float acc[4][4];
    #pragma unroll
    for (int an = 0; an < 4; an++)
        #pragma unroll
        for (int e = 0; e < 4; e++) acc[an][e] = 0.f;

    const int ib = wm * 16;
    for (int k0 = 0; k0 < vlen; k0 += 64) {
        #pragma unroll
        for (int it = 0; it < 16; it++) {
            int idx = tid + it * 256;
            int r = idx >> 6, c = idx & 63;
            as_s[r][c] = (i0 + r < NN && k0 + c < vlen)
                         ? __float_as_uint(attn[(size_t)(i0 + r) * NN + k0 + c]) : 0u;
            vs_s[r][c] = (k0 + r < NN) ? __float_as_uint(vb[(size_t)(k0 + r) * DHE + c]) : 0u;
        }
        __syncthreads();
        #pragma unroll
        for (int kk = 0; kk < 64; kk += 8) {
            uint32_t a0 = as_s[ib + g][kk + t];
            uint32_t a1 = as_s[ib + 8 + g][kk + t];
            uint32_t a2 = as_s[ib + g][kk + t + 4];
            uint32_t a3 = as_s[ib + 8 + g][kk + t + 4];
            #pragma unroll
            for (int an = 0; an < 4; an++) {
                int n = wn * 32 + an * 8 + g;
                uint32_t b0 = vs_s[kk + t][n];
                uint32_t b1 = vs_s[kk + t + 4][n];
                mma_tf32(acc[an], a0, a1, a2, a3, b0, b1);
            }
        }
        __syncthreads();
    }

    float* ob = g_ao + (size_t)x * NN * DHE;
    #pragma unroll
    for (int an = 0; an < 4; an++) {
        int dh = wn * 32 + an * 8 + 2 * t;
        #pragma unroll
        for (int hl = 0; hl < 2; hl++) {
            int i = i0 + ib + g + hl * 8;
            if (i < NN) {
                ob[(size_t)i * DHE + dh]     = __uint_as_float(f2tf(acc[an][hl * 2 + 0]));
                ob[(size_t)i * DHE + dh + 1] = __uint_as_float(f2tf(acc[an][hl * 2 + 1]));
            }
        }
    }
}

// ============================================================
// K5: output projection (tf32 mma) + bias + residual -> g_o (fp32)
// Block tile 128x64 like K1. A gathered head-major from g_ao (already tf32 bits).
// ============================================================
__global__ __launch_bounds__(256) void outproj_gemm(const float* __restrict__ W,
                                                    const float* __restrict__ bias,
                                                    const float* __restrict__ query)
{
    __shared__ uint32_t Xs[128][20];
    __shared__ uint32_t Bs[16][68];

    const int tid = threadIdx.x;
    const int lane = tid & 31, warp = tid >> 5;
    const int g = lane >> 2, t = lane & 3;
    const int wm = warp >> 1, wn = warp & 1;
    const int m0 = blockIdx.x * 128;
    const int n0 = blockIdx.y * 64;

    // precompute gather bases for the 8 staged rows this thread handles
    size_t pre[8];
    #pragma unroll
    for (int it = 0; it < 8; it++) {
        int idx = tid + it * 256;
        int r = idx >> 4;
        int m = m0 + r;
        int bb = m / NN, nn = m % NN;
        pre[it] = ((size_t)bb * NN + nn) * DHE;
    }

    float acc[2][4][4];
    #pragma unroll
    for (int am = 0; am < 2; am++)
        #pragma unroll
        for (int an = 0; an < 4; an++)
            #pragma unroll
            for (int e = 0; e < 4; e++) acc[am][an][e] = 0.f;

    for (int k0 = 0; k0 < DD; k0 += 16) {
        const int h = k0 >> 6;
        const int dh0 = k0 & 63;
        const size_t hoff = (size_t)h * BB * NN * DHE;
        #pragma unroll
        for (int it = 0; it < 8; it++) {
            int idx = tid + it * 256;
            int r = idx >> 4, c = idx & 15;
            Xs[r][c] = __float_as_uint(g_ao[hoff + pre[it] + dh0 + c]);
        }
        #pragma unroll
        for (int it = 0; it < 4; it++) {
            int idx = tid + it * 256;
            int kr = idx >> 6, c = idx & 63;
            Bs[kr][c] = f2tf(W[(size_t)(k0 + kr) * DD + n0 + c]);
        }
        __syncthreads();

        #pragma unroll
        for (int ks = 0; ks < 16; ks += 8) {
            uint32_t a[2][4];
            #pragma unroll
            for (int am = 0; am < 2; am++) {
                int row = wm * 32 + am * 16;
                a[am][0] = Xs[row + g][ks + t];
                a[am][1] = Xs[row + 8 + g][ks + t];
                a[am][2] = Xs[row + g][ks + t + 4];
                a[am][3] = Xs[row + 8 + g][ks + t + 4];
            }
            #pragma unroll
            for (int an = 0; an < 4; an++) {
                int n = wn * 32 + an * 8 + g;
                uint32_t b0 = Bs[ks + t][n];
                uint32_t b1 = Bs[ks + t + 4][n];
                mma_tf32(acc[0][an], a[0][0], a[0][1], a[0][2], a[0][3], b0, b1);
                mma_tf32(acc[1][an], a[1][0], a[1][1], a[1][2], a[1][3], b0, b1);
            }
        }
        __syncthreads();
    }

    #pragma unroll
    for (int an = 0; an < 4; an++) {
        int col = n0 + wn * 32 + an * 8 + 2 * t;
        #pragma unroll
        for (int cc = 0; cc < 2; cc++) {
            int e = col + cc;
            float bv_ = bias[e];
            #pragma unroll
            for (int am = 0; am < 2; am++)
                #pragma unroll
                for (int hl = 0; hl < 2; hl++) {
                    int m = m0 + wm * 32 + am * 16 + g + hl * 8;
                    g_o[(size_t)m * DD + e] =
                        acc[am][an][hl * 2 + cc] + bv_ + query[(size_t)m * DD + e];
                }
        }
    }
}

// ============================================================
// K6: LayerNorm over D=512 per row -> d_out
// ============================================================
__global__ __launch_bounds__(256) void ln_kernel(const float* __restrict__ gamma,
                                                 const float* __restrict__ beta,
                                                 float* __restrict__ out)
{
    const int m = blockIdx.x;
    const float* xr = g_o + (size_t)m * DD;
    const int tid = threadIdx.x;

    __shared__ float red[8];

    float x0 = xr[tid], x1 = xr[tid + 256];
    float s = x0 + x1;
    #pragma unroll
    for (int off = 16; off > 0; off >>= 1)
        s += __shfl_xor_sync(0xffffffff, s, off);
    if ((tid & 31) == 0) red[tid >> 5] = s;
    __syncthreads();
    float tot = 0.f;
    #pragma unroll
    for (int w = 0; w < 8; w++) tot += red[w];
    float mean = tot * (1.f / DD);

    float d0 = x0 - mean, d1 = x1 - mean;
    float ss = d0 * d0 + d1 * d1;
    #pragma unroll
    for (int off = 16; off > 0; off >>= 1)
        ss += __shfl_xor_sync(0xffffffff, ss, off);
    __syncthreads();
    if ((tid & 31) == 0) red[tid >> 5] = ss;
    __syncthreads();
    float tss = 0.f;
    #pragma unroll
    for (int w = 0; w < 8; w++) tss += red[w];
    float var = tss * (1.f / DD);
    float rstd = rsqrtf(var + 1e-7f);

    out[(size_t)m * DD + tid]       = gamma[tid]       * d0 * rstd + beta[tid];
    out[(size_t)m * DD + tid + 256] = gamma[tid + 256] * d1 * rstd + beta[tid + 256];
}

// ============================================================
extern "C" void kernel_launch(void* const* d_in, const int* in_sizes, int n_in,
                              void* d_out, int out_size)
{
    const float* query = (const float*)d_in[0];
    const float* Wq    = (const float*)d_in[1];
    const float* bq    = (const float*)d_in[2];
    const float* Wk    = (const float*)d_in[3];
    const float* bk    = (const float*)d_in[4];
    const float* Wv    = (const float*)d_in[5];
    const float* bv    = (const float*)d_in[6];
    const float* Wh    = (const float*)d_in[7];
    const float* bh    = (const float*)d_in[8];
    const float* pos_k = (const float*)d_in[9];
    const float* gamma = (const float*)d_in[10];
    const float* beta  = (const float*)d_in[11];
    const int*   vl    = (const int*)d_in[12];
    float* out = (float*)d_out;

    qkv_fused<<<dim3(BN / 128, DD / 64), 256>>>(query, Wq, bq, Wk, bk, Wv, bv);

    qk_kernel<<<dim3(9, 9, HB), 256>>>(vl);
    qr_kernel<<<dim3(17, 9, HB), 256>>>(pos_k, vl);

    softmax_kernel<<<dim3(NN, HB), 256>>>(vl);
    av_kernel<<<dim3(9, HB), 256>>>(vl);

    outproj_gemm<<<dim3(BN / 128, DD / 64), 256>>>(Wh, bh, query);
    ln_kernel<<<BN, 256>>>(gamma, beta, out);
}

// round 3
// speedup vs baseline: 3.1481x; 2.0498x over previous
#include <cuda_runtime.h>
#include <cstdint>
#include <math.h>

#define BB 32
#define NN 540
#define DD 512
#define HH 8
#define DHE 64
#define HB (HH*BB)          // 256
#define BN (BB*NN)          // 17280
#define PCLIP 539
#define RLEN (2*PCLIP+1)    // 1079

// -------- scratch (device globals) --------
__device__ float g_q[(size_t)HB*NN*DHE];   // tf32 bits, q pre-scaled by 0.125
__device__ float g_k[(size_t)HB*NN*DHE];   // tf32 bits
__device__ float g_v[(size_t)HB*NN*DHE];   // tf32 bits
__device__ float g_r[(size_t)HB*NN*NN];    // relative-position bias QR (fp32), j<vlen
__device__ float g_ao[(size_t)HB*NN*DHE];  // attn@v, tf32 bits, head-major
__device__ float g_o[(size_t)BN*DD];       // pre-LN (fp32)

// -------- helpers --------
__device__ __forceinline__ uint32_t f2tf(float f) {
    uint32_t u;
    asm("cvt.rna.tf32.f32 %0, %1;" : "=r"(u) : "f"(f));
    return u;
}

__device__ __forceinline__ void mma_tf32(float c[4],
                                         uint32_t a0, uint32_t a1, uint32_t a2, uint32_t a3,
                                         uint32_t b0, uint32_t b1) {
    asm volatile(
        "mma.sync.aligned.m16n8k8.row.col.f32.tf32.tf32.f32 "
        "{%0,%1,%2,%3}, {%4,%5,%6,%7}, {%8,%9}, {%0,%1,%2,%3};\n"
        : "+f"(c[0]), "+f"(c[1]), "+f"(c[2]), "+f"(c[3])
        : "r"(a0), "r"(a1), "r"(a2), "r"(a3), "r"(b0), "r"(b1));
}

// ============================================================
// K1: fused QKV projection, tf32 mma. Block tile 128x64, 8 warps.
// ============================================================
__global__ __launch_bounds__(256) void qkv_fused(const float* __restrict__ X,
                                                 const float* __restrict__ Wq, const float* __restrict__ bq,
                                                 const float* __restrict__ Wk, const float* __restrict__ bk,
                                                 const float* __restrict__ Wv, const float* __restrict__ bv)
{
    __shared__ uint32_t Xs[128][20];
    __shared__ uint32_t Bs[3][16][68];

    const int tid = threadIdx.x;
    const int lane = tid & 31, warp = tid >> 5;
    const int g = lane >> 2, t = lane & 3;
    const int wm = warp >> 1, wn = warp & 1;
    const int m0 = blockIdx.x * 128;
    const int n0 = blockIdx.y * 64;

    const float* Ws[3] = {Wq, Wk, Wv};

    float acc[3][2][4][4];
    #pragma unroll
    for (int w = 0; w < 3; w++)
        #pragma unroll
        for (int am = 0; am < 2; am++)
            #pragma unroll
            for (int an = 0; an < 4; an++)
                #pragma unroll
                for (int e = 0; e < 4; e++) acc[w][am][an][e] = 0.f;

    for (int k0 = 0; k0 < DD; k0 += 16) {
        #pragma unroll
        for (int it = 0; it < 8; it++) {
            int idx = tid + it * 256;
            int r = idx >> 4, c = idx & 15;
            Xs[r][c] = f2tf(X[(size_t)(m0 + r) * DD + k0 + c]);
        }
        #pragma unroll
        for (int w = 0; w < 3; w++) {
            const float* W = Ws[w];
            #pragma unroll
            for (int it = 0; it < 4; it++) {
                int idx = tid + it * 256;
                int kr = idx >> 6, c = idx & 63;
                Bs[w][kr][c] = f2tf(W[(size_t)(k0 + kr) * DD + n0 + c]);
            }
        }
        __syncthreads();

        #pragma unroll
        for (int ks = 0; ks < 16; ks += 8) {
            uint32_t a[2][4];
            #pragma unroll
            for (int am = 0; am < 2; am++) {
                int row = wm * 32 + am * 16;
                a[am][0] = Xs[row + g][ks + t];
                a[am][1] = Xs[row + 8 + g][ks + t];
                a[am][2] = Xs[row + g][ks + t + 4];
                a[am][3] = Xs[row + 8 + g][ks + t + 4];
            }
            #pragma unroll
            for (int w = 0; w < 3; w++) {
                #pragma unroll
                for (int an = 0; an < 4; an++) {
                    int n = wn * 32 + an * 8 + g;
                    uint32_t b0 = Bs[w][ks + t][n];
                    uint32_t b1 = Bs[w][ks + t + 4][n];
                    mma_tf32(acc[w][0][an], a[0][0], a[0][1], a[0][2], a[0][3], b0, b1);
                    mma_tf32(acc[w][1][an], a[1][0], a[1][1], a[1][2], a[1][3], b0, b1);
                }
            }
        }
        __syncthreads();
    }

    int mb[2][2], mn[2][2];
    #pragma unroll
    for (int am = 0; am < 2; am++)
        #pragma unroll
        for (int hl = 0; hl < 2; hl++) {
            int m = m0 + wm * 32 + am * 16 + g + hl * 8;
            mb[am][hl] = m / NN;
            mn[am][hl] = m % NN;
        }

    const float* biases[3] = {bq, bk, bv};
    #pragma unroll
    for (int w = 0; w < 3; w++) {
        float* out = (w == 0) ? g_q : (w == 1) ? g_k : g_v;
        const float* bias = biases[w];
        float scl = (w == 0) ? 0.125f : 1.0f;
        #pragma unroll
        for (int an = 0; an < 4; an++) {
            int col = n0 + wn * 32 + an * 8 + 2 * t;
            #pragma unroll
            for (int cc = 0; cc < 2; cc++) {
                int e = col + cc;
                int h = e >> 6, dh = e & 63;
                float bv_ = bias[e];
                #pragma unroll
                for (int am = 0; am < 2; am++)
                    #pragma unroll
                    for (int hl = 0; hl < 2; hl++) {
                        float val = (acc[w][am][an][hl * 2 + cc] + bv_) * scl;
                        out[((size_t)(h * BB + mb[am][hl]) * NN + mn[am][hl]) * DHE + dh]
                            = __uint_as_float(f2tf(val));
                    }
            }
        }
    }
}

// ============================================================
// K2: QR banded GEMM -> pure store into g_r[x][i][j], j in [0, vlen).
// T[x,i,r] = q_i · pos_k[r]; j = r + i - 539.
// ============================================================
__global__ __launch_bounds__(256) void qr_kernel(const float* __restrict__ pos_k,
                                                 const int* __restrict__ vl)
{
    __shared__ uint32_t qs[64][68];
    __shared__ uint32_t ps[64][68];

    const int x = blockIdx.z;
    const int b = x & (BB - 1);
    const int vlen = vl[b];
    const int r0 = blockIdx.x * 64;
    const int i0 = blockIdx.y * 64;
    if (r0 + i0 + 126 - PCLIP < 0) return;
    if (r0 + i0 - PCLIP >= vlen) return;

    const int tid = threadIdx.x;
    const int lane = tid & 31, warp = tid >> 5;
    const int g = lane >> 2, t = lane & 3;
    const int wm = warp >> 1, wn = warp & 1;

    const float* qb = g_q + (size_t)x * NN * DHE;

    #pragma unroll
    for (int it = 0; it < 16; it++) {
        int idx = tid + it * 256;
        int r = idx >> 6, c = idx & 63;
        qs[r][c] = (i0 + r < NN) ? __float_as_uint(qb[(size_t)(i0 + r) * DHE + c]) : 0u;
        ps[r][c] = (r0 + r < RLEN) ? f2tf(pos_k[(size_t)(r0 + r) * DHE + c]) : 0u;
    }
    __syncthreads();

    float acc[4][4];
    #pragma unroll
    for (int an = 0; an < 4; an++)
        #pragma unroll
        for (int e = 0; e < 4; e++) acc[an][e] = 0.f;

    const int ib = wm * 16;
    #pragma unroll
    for (int kk = 0; kk < 64; kk += 8) {
        uint32_t a0 = qs[ib + g][kk + t];
        uint32_t a1 = qs[ib + 8 + g][kk + t];
        uint32_t a2 = qs[ib + g][kk + t + 4];
        uint32_t a3 = qs[ib + 8 + g][kk + t + 4];
        #pragma unroll
        for (int an = 0; an < 4; an++) {
            int n = wn * 32 + an * 8 + g;
            uint32_t b0 = ps[n][kk + t];
            uint32_t b1 = ps[n][kk + t + 4];
            mma_tf32(acc[an], a0, a1, a2, a3, b0, b1);
        }
    }

    float* rrow = g_r + (size_t)x * NN * NN;
    #pragma unroll
    for (int an = 0; an < 4; an++) {
        int rr = r0 + wn * 32 + an * 8 + 2 * t;
        #pragma unroll
        for (int hl = 0; hl < 2; hl++) {
            int i = i0 + ib + g + hl * 8;
            if (i < NN) {
                #pragma unroll
                for (int cc = 0; cc < 2; cc++) {
                    int j = rr + cc + i - PCLIP;
                    if (j >= 0 && j < vlen)
                        rrow[(size_t)i * NN + j] = acc[an][hl * 2 + cc];
                }
            }
        }
    }
}

// ============================================================
// K3: flash attention: S = q·k^T + g_r, online softmax, O = P·v.
// Block: one x, one 64-row i-tile. 128 threads (4 warps x 16 rows).
// Dynamic smem: qs/ks/vs/ps, each 64x68 u32 = 68 KB.
// ============================================================
__global__ __launch_bounds__(128) void flash_kernel(const int* __restrict__ vl)
{
    extern __shared__ uint32_t smbuf[];
    uint32_t (*qs)[68] = (uint32_t(*)[68])smbuf;
    uint32_t (*ks)[68] = (uint32_t(*)[68])(smbuf + 64 * 68);
    uint32_t (*vs)[68] = (uint32_t(*)[68])(smbuf + 2 * 64 * 68);
    uint32_t (*ps)[68] = (uint32_t(*)[68])(smbuf + 3 * 64 * 68);

    const int x = blockIdx.y;
    const int b = x & (BB - 1);
    const int vlen = vl[b];
    const int i0 = blockIdx.x * 64;

    const int tid = threadIdx.x;
    const int lane = tid & 31, warp = tid >> 5;
    const int g = lane >> 2, t = lane & 3;
    const int ib = warp * 16;

    const float* qb = g_q + (size_t)x * NN * DHE;
    const float* kb = g_k + (size_t)x * NN * DHE;
    const float* vb = g_v + (size_t)x * NN * DHE;
    const float* rb = g_r + (size_t)x * NN * NN;

    // load q tile once (tf32 bits), LDG.128
    #pragma unroll
    for (int it = 0; it < 8; it++) {
        int idx = tid + it * 128;
        int r = idx >> 4, c4 = (idx & 15) * 4;
        uint4 val = make_uint4(0u, 0u, 0u, 0u);
        if (i0 + r < NN) val = *(const uint4*)(qb + (size_t)(i0 + r) * DHE + c4);
        qs[r][c4] = val.x; qs[r][c4 + 1] = val.y; qs[r][c4 + 2] = val.z; qs[r][c4 + 3] = val.w;
    }

    const int irow0 = i0 + ib + g;
    const int irow1 = irow0 + 8;
    const bool iok0 = irow0 < NN, iok1 = irow1 < NN;

    float m0 = -1e30f, m1 = -1e30f, l0 = 0.f, l1 = 0.f;
    float oacc[8][4];
    #pragma unroll
    for (int fn = 0; fn < 8; fn++)
        #pragma unroll
        for (int e = 0; e < 4; e++) oacc[fn][e] = 0.f;

    for (int j0 = 0; j0 < vlen; j0 += 64) {
        __syncthreads();   // previous AV done with vs, QK done with ks
        #pragma unroll
        for (int it = 0; it < 8; it++) {
            int idx = tid + it * 128;
            int r = idx >> 4, c4 = (idx & 15) * 4;
            uint4 kv = make_uint4(0u, 0u, 0u, 0u), vv = make_uint4(0u, 0u, 0u, 0u);
            if (j0 + r < NN) {
                kv = *(const uint4*)(kb + (size_t)(j0 + r) * DHE + c4);
                vv = *(const uint4*)(vb + (size_t)(j0 + r) * DHE + c4);
            }
            ks[r][c4] = kv.x; ks[r][c4 + 1] = kv.y; ks[r][c4 + 2] = kv.z; ks[r][c4 + 3] = kv.w;
            vs[r][c4] = vv.x; vs[r][c4 + 1] = vv.y; vs[r][c4 + 2] = vv.z; vs[r][c4 + 3] = vv.w;
        }
        __syncthreads();

        // ---- S = q · k^T ----
        float sacc[8][4];
        #pragma unroll
        for (int fn = 0; fn < 8; fn++)
            #pragma unroll
            for (int e = 0; e < 4; e++) sacc[fn][e] = 0.f;

        #pragma unroll
        for (int kk = 0; kk < 64; kk += 8) {
            uint32_t a0 = qs[ib + g][kk + t];
            uint32_t a1 = qs[ib + 8 + g][kk + t];
            uint32_t a2 = qs[ib + g][kk + t + 4];
            uint32_t a3 = qs[ib + 8 + g][kk + t + 4];
            #pragma unroll
            for (int fn = 0; fn < 8; fn++) {
                int n = fn * 8 + g;
                mma_tf32(sacc[fn], a0, a1, a2, a3, ks[n][kk + t], ks[n][kk + t + 4]);
            }
        }

        // ---- add relative bias + mask; tile row max ----
        float tm0 = -1e30f, tm1 = -1e30f;
        #pragma unroll
        for (int fn = 0; fn < 8; fn++) {
            int j = j0 + fn * 8 + 2 * t;
            float r00 = -1e30f, r01 = -1e30f, r10 = -1e30f, r11 = -1e30f;
            if (j < vlen) {
                if (j + 1 < vlen) {
                    if (iok0) { float2 rr = *(const float2*)(rb + (size_t)irow0 * NN + j); r00 = rr.x; r01 = rr.y; }
                    if (iok1) { float2 rr = *(const float2*)(rb + (size_t)irow1 * NN + j); r10 = rr.x; r11 = rr.y; }
                } else {
                    if (iok0) r00 = rb[(size_t)irow0 * NN + j];
                    if (iok1) r10 = rb[(size_t)irow1 * NN + j];
                }
            }
            sacc[fn][0] += r00; sacc[fn][1] += r01;
            sacc[fn][2] += r10; sacc[fn][3] += r11;
            tm0 = fmaxf(tm0, fmaxf(sacc[fn][0], sacc[fn][1]));
            tm1 = fmaxf(tm1, fmaxf(sacc[fn][2], sacc[fn][3]));
        }
        tm0 = fmaxf(tm0, __shfl_xor_sync(0xffffffffu, tm0, 1));
        tm0 = fmaxf(tm0, __shfl_xor_sync(0xffffffffu, tm0, 2));
        tm1 = fmaxf(tm1, __shfl_xor_sync(0xffffffffu, tm1, 1));
        tm1 = fmaxf(tm1, __shfl_xor_sync(0xffffffffu, tm1, 2));

        float mn0 = fmaxf(m0, tm0), mn1 = fmaxf(m1, tm1);
        float sc0 = __expf(m0 - mn0), sc1 = __expf(m1 - mn1);
        m0 = mn0; m1 = mn1;

        // ---- exp, stage P (tf32), row sums ----
        float tl0 = 0.f, tl1 = 0.f;
        #pragma unroll
        for (int fn = 0; fn < 8; fn++) {
            float p00 = __expf(sacc[fn][0] - mn0);
            float p01 = __expf(sacc[fn][1] - mn0);
            float p10 = __expf(sacc[fn][2] - mn1);
            float p11 = __expf(sacc[fn][3] - mn1);
            tl0 += p00 + p01; tl1 += p10 + p11;
            int c0 = fn * 8 + 2 * t;
            ps[ib + g][c0]         = f2tf(p00);
            ps[ib + g][c0 + 1]     = f2tf(p01);
            ps[ib + 8 + g][c0]     = f2tf(p10);
            ps[ib + 8 + g][c0 + 1] = f2tf(p11);
        }
        tl0 += __shfl_xor_sync(0xffffffffu, tl0, 1);
        tl0 += __shfl_xor_sync(0xffffffffu, tl0, 2);
        tl1 += __shfl_xor_sync(0xffffffffu, tl1, 1);
        tl1 += __shfl_xor_sync(0xffffffffu, tl1, 2);
        l0 = l0 * sc0 + tl0;
        l1 = l1 * sc1 + tl1;

        // rescale O accumulators
        #pragma unroll
        for (int fn = 0; fn < 8; fn++) {
            oacc[fn][0] *= sc0; oacc[fn][1] *= sc0;
            oacc[fn][2] *= sc1; oacc[fn][3] *= sc1;
        }

        __syncwarp();

        // ---- O += P · V ----
        #pragma unroll
        for (int kk = 0; kk < 64; kk += 8) {
            uint32_t a0 = ps[ib + g][kk + t];
            uint32_t a1 = ps[ib + 8 + g][kk + t];
            uint32_t a2 = ps[ib + g][kk + t + 4];
            uint32_t a3 = ps[ib + 8 + g][kk + t + 4];
            #pragma unroll
            for (int fn = 0; fn < 8; fn++) {
                int n = fn * 8 + g;
                mma_tf32(oacc[fn], a0, a1, a2, a3, vs[kk + t][n], vs[kk + t + 4][n]);
            }
        }
        __syncwarp();
    }

    // ---- finalize: divide by row sums, store tf32 bits ----
    float inv0 = 1.f / l0, inv1 = 1.f / l1;
    float* ob = g_ao + (size_t)x * NN * DHE;
    #pragma unroll
    for (int fn = 0; fn < 8; fn++) {
        int dh = fn * 8 + 2 * t;
        if (iok0) {
            float2 v;
            v.x = __uint_as_float(f2tf(oacc[fn][0] * inv0));
            v.y = __uint_as_float(f2tf(oacc[fn][1] * inv0));
            *(float2*)(ob + (size_t)irow0 * DHE + dh) = v;
        }
        if (iok1) {
            float2 v;
            v.x = __uint_as_float(f2tf(oacc[fn][2] * inv1));
            v.y = __uint_as_float(f2tf(oacc[fn][3] * inv1));
            *(float2*)(ob + (size_t)irow1 * DHE + dh) = v;
        }
    }
}

// ============================================================
// K5: output projection (tf32 mma) + bias + residual -> g_o (fp32)
// ============================================================
__global__ __launch_bounds__(256) void outproj_gemm(const float* __restrict__ W,
                                                    const float* __restrict__ bias,
                                                    const float* __restrict__ query)
{
    __shared__ uint32_t Xs[128][20];
    __shared__ uint32_t Bs[16][68];

    const int tid = threadIdx.x;
    const int lane = tid & 31, warp = tid >> 5;
    const int g = lane >> 2, t = lane & 3;
    const int wm = warp >> 1, wn = warp & 1;
    const int m0 = blockIdx.x * 128;
    const int n0 = blockIdx.y * 64;

    size_t pre[8];
    #pragma unroll
    for (int it = 0; it < 8; it++) {
        int idx = tid + it * 256;
        int r = idx >> 4;
        int m = m0 + r;
        int bb = m / NN, nn = m % NN;
        pre[it] = ((size_t)bb * NN + nn) * DHE;
    }

    float acc[2][4][4];
    #pragma unroll
    for (int am = 0; am < 2; am++)
        #pragma unroll
        for (int an = 0; an < 4; an++)
            #pragma unroll
            for (int e = 0; e < 4; e++) acc[am][an][e] = 0.f;

    for (int k0 = 0; k0 < DD; k0 += 16) {
        const int h = k0 >> 6;
        const int dh0 = k0 & 63;
        const size_t hoff = (size_t)h * BB * NN * DHE;
        #pragma unroll
        for (int it = 0; it < 8; it++) {
            int idx = tid + it * 256;
            int r = idx >> 4, c = idx & 15;
            Xs[r][c] = __float_as_uint(g_ao[hoff + pre[it] + dh0 + c]);
        }
        #pragma unroll
        for (int it = 0; it < 4; it++) {
            int idx = tid + it * 256;
            int kr = idx >> 6, c = idx & 63;
            Bs[kr][c] = f2tf(W[(size_t)(k0 + kr) * DD + n0 + c]);
        }
        __syncthreads();

        #pragma unroll
        for (int ks = 0; ks < 16; ks += 8) {
            uint32_t a[2][4];
            #pragma unroll
            for (int am = 0; am < 2; am++) {
                int row = wm * 32 + am * 16;
                a[am][0] = Xs[row + g][ks + t];
                a[am][1] = Xs[row + 8 + g][ks + t];
                a[am][2] = Xs[row + g][ks + t + 4];
                a[am][3] = Xs[row + 8 + g][ks + t + 4];
            }
            #pragma unroll
            for (int an = 0; an < 4; an++) {
                int n = wn * 32 + an * 8 + g;
                uint32_t b0 = Bs[ks + t][n];
                uint32_t b1 = Bs[ks + t + 4][n];
                mma_tf32(acc[0][an], a[0][0], a[0][1], a[0][2], a[0][3], b0, b1);
                mma_tf32(acc[1][an], a[1][0], a[1][1], a[1][2], a[1][3], b0, b1);
            }
        }
        __syncthreads();
    }

    #pragma unroll
    for (int an = 0; an < 4; an++) {
        int col = n0 + wn * 32 + an * 8 + 2 * t;
        #pragma unroll
        for (int cc = 0; cc < 2; cc++) {
            int e = col + cc;
            float bv_ = bias[e];
            #pragma unroll
            for (int am = 0; am < 2; am++)
                #pragma unroll
                for (int hl = 0; hl < 2; hl++) {
                    int m = m0 + wm * 32 + am * 16 + g + hl * 8;
                    g_o[(size_t)m * DD + e] =
                        acc[am][an][hl * 2 + cc] + bv_ + query[(size_t)m * DD + e];
                }
        }
    }
}

// ============================================================
// K6: LayerNorm over D=512 per row -> d_out
// ============================================================
__global__ __launch_bounds__(256) void ln_kernel(const float* __restrict__ gamma,
                                                 const float* __restrict__ beta,
                                                 float* __restrict__ out)
{
    const int m = blockIdx.x;
    const float* xr = g_o + (size_t)m * DD;
    const int tid = threadIdx.x;

    __shared__ float red[8];

    float x0 = xr[tid], x1 = xr[tid + 256];
    float s = x0 + x1;
    #pragma unroll
    for (int off = 16; off > 0; off >>= 1)
        s += __shfl_xor_sync(0xffffffff, s, off);
    if ((tid & 31) == 0) red[tid >> 5] = s;
    __syncthreads();
    float tot = 0.f;
    #pragma unroll
    for (int w = 0; w < 8; w++) tot += red[w];
    float mean = tot * (1.f / DD);

    float d0 = x0 - mean, d1 = x1 - mean;
    float ss = d0 * d0 + d1 * d1;
    #pragma unroll
    for (int off = 16; off > 0; off >>= 1)
        ss += __shfl_xor_sync(0xffffffff, ss, off);
    __syncthreads();
    if ((tid & 31) == 0) red[tid >> 5] = ss;
    __syncthreads();
    float tss = 0.f;
    #pragma unroll
    for (int w = 0; w < 8; w++) tss += red[w];
    float var = tss * (1.f / DD);
    float rstd = rsqrtf(var + 1e-7f);

    out[(size_t)m * DD + tid]       = gamma[tid]       * d0 * rstd + beta[tid];
    out[(size_t)m * DD + tid + 256] = gamma[tid + 256] * d1 * rstd + beta[tid + 256];
}

// ============================================================
extern "C" void kernel_launch(void* const* d_in, const int* in_sizes, int n_in,
                              void* d_out, int out_size)
{
    const float* query = (const float*)d_in[0];
    const float* Wq    = (const float*)d_in[1];
    const float* bq    = (const float*)d_in[2];
    const float* Wk    = (const float*)d_in[3];
    const float* bk    = (const float*)d_in[4];
    const float* Wv    = (const float*)d_in[5];
    const float* bv    = (const float*)d_in[6];
    const float* Wh    = (const float*)d_in[7];
    const float* bh    = (const float*)d_in[8];
    const float* pos_k = (const float*)d_in[9];
    const float* gamma = (const float*)d_in[10];
    const float* beta  = (const float*)d_in[11];
    const int*   vl    = (const int*)d_in[12];
    float* out = (float*)d_out;

    static int smem_set = 0;
    const int FLASH_SMEM = 4 * 64 * 68 * 4;   // 69632 bytes
    if (!smem_set) {
        cudaFuncSetAttribute(flash_kernel,
                             cudaFuncAttributeMaxDynamicSharedMemorySize, FLASH_SMEM);
        smem_set = 1;
    }

    qkv_fused<<<dim3(BN / 128, DD / 64), 256>>>(query, Wq, bq, Wk, bk, Wv, bv);

    qr_kernel<<<dim3(17, 9, HB), 256>>>(pos_k, vl);

    flash_kernel<<<dim3(9, HB), 128, FLASH_SMEM>>>(vl);

    outproj_gemm<<<dim3(BN / 128, DD / 64), 256>>>(Wh, bh, query);
    ln_kernel<<<BN, 256>>>(gamma, beta, out);
}

// round 4
// speedup vs baseline: 3.8502x; 1.2230x over previous
#include <cuda_runtime.h>
#include <cstdint>
#include <math.h>

#define BB 32
#define NN 540
#define DD 512
#define HH 8
#define DHE 64
#define HB (HH*BB)          // 256
#define BN (BB*NN)          // 17280
#define PCLIP 539
#define RLEN (2*PCLIP+1)    // 1079

// -------- scratch (device globals) --------
__device__ float g_q[(size_t)HB*NN*DHE];   // tf32 bits, q pre-scaled by 0.125
__device__ float g_k[(size_t)HB*NN*DHE];   // tf32 bits
__device__ float g_v[(size_t)HB*NN*DHE];   // tf32 bits
__device__ float g_r[(size_t)HB*NN*NN];    // relative-position bias QR (fp32), j<vlen
__device__ float g_ao[(size_t)HB*NN*DHE];  // attn@v, tf32 bits, head-major
__device__ float g_o[(size_t)BN*DD];       // pre-LN (fp32)

// -------- helpers --------
__device__ __forceinline__ uint32_t f2tf(float f) {
    uint32_t u;
    asm("cvt.rna.tf32.f32 %0, %1;" : "=r"(u) : "f"(f));
    return u;
}

__device__ __forceinline__ void mma_tf32(float c[4],
                                         uint32_t a0, uint32_t a1, uint32_t a2, uint32_t a3,
                                         uint32_t b0, uint32_t b1) {
    asm volatile(
        "mma.sync.aligned.m16n8k8.row.col.f32.tf32.tf32.f32 "
        "{%0,%1,%2,%3}, {%4,%5,%6,%7}, {%8,%9}, {%0,%1,%2,%3};\n"
        : "+f"(c[0]), "+f"(c[1]), "+f"(c[2]), "+f"(c[3])
        : "r"(a0), "r"(a1), "r"(a2), "r"(a3), "r"(b0), "r"(b1));
}

__device__ __forceinline__ void cp16(uint32_t smem_u32_addr, const void* gptr) {
    asm volatile("cp.async.cg.shared.global [%0], [%1], 16;\n"
                 :: "r"(smem_u32_addr), "l"(gptr));
}
#define CP_COMMIT() asm volatile("cp.async.commit_group;\n" ::)
#define CP_WAIT(n)  asm volatile("cp.async.wait_group %0;\n" :: "n"(n))

// smem tiling constants for pipelined GEMMs
#define XS_STRIDE 36
#define X_TILE_U32 (128*XS_STRIDE)     // 4608
#define BS_STRIDE 68
#define B_TILE_U32 (32*BS_STRIDE)      // 2176

// ============================================================
// K1: fused QKV projection, tf32 mma, cp.async 2-stage pipeline.
// Block tile 128x64, K-panel 32, 8 warps (4m x 2n), warp tile 32x32.
// Raw fp32 bits fed to tf32 mma (truncation).
// ============================================================
__global__ __launch_bounds__(256) void qkv_fused(const float* __restrict__ X,
                                                 const float* __restrict__ Wq, const float* __restrict__ bq,
                                                 const float* __restrict__ Wk, const float* __restrict__ bk,
                                                 const float* __restrict__ Wv, const float* __restrict__ bv)
{
    extern __shared__ uint32_t smbuf[];
    // Xs: [2][128][36] at 0 ; Bs: [2][3][32][68] at 2*X_TILE_U32
    const uint32_t smem_base = (uint32_t)__cvta_generic_to_shared(smbuf);

    const int tid = threadIdx.x;
    const int lane = tid & 31, warp = tid >> 5;
    const int g = lane >> 2, t = lane & 3;
    const int wm = warp >> 1, wn = warp & 1;
    const int m0 = blockIdx.x * 128;
    const int n0 = blockIdx.y * 64;

    const float* Ws[3] = {Wq, Wk, Wv};

    // per-thread load coordinates (fixed)
    const int xrow[4] = { (tid) >> 3, (tid + 256) >> 3, (tid + 512) >> 3, (tid + 768) >> 3 };
    const int xcol4 = (tid & 7) * 4;
    const int brow[2] = { tid >> 4, (tid + 256) >> 4 };
    const int bcol4 = (tid & 15) * 4;

    float acc[3][2][4][4];
    #pragma unroll
    for (int w = 0; w < 3; w++)
        #pragma unroll
        for (int am = 0; am < 2; am++)
            #pragma unroll
            for (int an = 0; an < 4; an++)
                #pragma unroll
                for (int e = 0; e < 4; e++) acc[w][am][an][e] = 0.f;

    // ---- panel loader ----
    auto load_panel = [&](int stage, int k0) {
        uint32_t xs = smem_base + (stage * X_TILE_U32) * 4;
        #pragma unroll
        for (int i = 0; i < 4; i++) {
            cp16(xs + (xrow[i] * XS_STRIDE + xcol4) * 4,
                 X + (size_t)(m0 + xrow[i]) * DD + k0 + xcol4);
        }
        #pragma unroll
        for (int w = 0; w < 3; w++) {
            uint32_t bs = smem_base + (2 * X_TILE_U32 + (stage * 3 + w) * B_TILE_U32) * 4;
            #pragma unroll
            for (int i = 0; i < 2; i++) {
                cp16(bs + (brow[i] * BS_STRIDE + bcol4) * 4,
                     Ws[w] + (size_t)(k0 + brow[i]) * DD + n0 + bcol4);
            }
        }
    };

    uint32_t (*Xsv)[XS_STRIDE] = (uint32_t(*)[XS_STRIDE])smbuf;
    uint32_t (*Bsv)[BS_STRIDE] = (uint32_t(*)[BS_STRIDE])(smbuf + 2 * X_TILE_U32);

    load_panel(0, 0);
    CP_COMMIT();

    const int NP = DD / 32;   // 16 panels
    for (int kt = 0; kt < NP; kt++) {
        if (kt + 1 < NP) {
            load_panel((kt + 1) & 1, (kt + 1) * 32);
            CP_COMMIT();
            CP_WAIT(1);
        } else {
            CP_WAIT(0);
        }
        __syncthreads();

        const int st = kt & 1;
        uint32_t (*Xs)[XS_STRIDE] = Xsv + st * 128;
        #pragma unroll
        for (int ks = 0; ks < 32; ks += 8) {
            uint32_t a[2][4];
            #pragma unroll
            for (int am = 0; am < 2; am++) {
                int row = wm * 32 + am * 16;
                a[am][0] = Xs[row + g][ks + t];
                a[am][1] = Xs[row + 8 + g][ks + t];
                a[am][2] = Xs[row + g][ks + t + 4];
                a[am][3] = Xs[row + 8 + g][ks + t + 4];
            }
            #pragma unroll
            for (int w = 0; w < 3; w++) {
                uint32_t (*Bs)[BS_STRIDE] = Bsv + (st * 3 + w) * 32;
                #pragma unroll
                for (int an = 0; an < 4; an++) {
                    int n = wn * 32 + an * 8 + g;
                    uint32_t b0 = Bs[ks + t][n];
                    uint32_t b1 = Bs[ks + t + 4][n];
                    mma_tf32(acc[w][0][an], a[0][0], a[0][1], a[0][2], a[0][3], b0, b1);
                    mma_tf32(acc[w][1][an], a[1][0], a[1][1], a[1][2], a[1][3], b0, b1);
                }
            }
        }
        __syncthreads();
    }

    int mb[2][2], mn[2][2];
    #pragma unroll
    for (int am = 0; am < 2; am++)
        #pragma unroll
        for (int hl = 0; hl < 2; hl++) {
            int m = m0 + wm * 32 + am * 16 + g + hl * 8;
            mb[am][hl] = m / NN;
            mn[am][hl] = m % NN;
        }

    const float* biases[3] = {bq, bk, bv};
    #pragma unroll
    for (int w = 0; w < 3; w++) {
        float* out = (w == 0) ? g_q : (w == 1) ? g_k : g_v;
        const float* bias = biases[w];
        float scl = (w == 0) ? 0.125f : 1.0f;
        #pragma unroll
        for (int an = 0; an < 4; an++) {
            int col = n0 + wn * 32 + an * 8 + 2 * t;
            #pragma unroll
            for (int cc = 0; cc < 2; cc++) {
                int e = col + cc;
                int h = e >> 6, dh = e & 63;
                float bv_ = bias[e];
                #pragma unroll
                for (int am = 0; am < 2; am++)
                    #pragma unroll
                    for (int hl = 0; hl < 2; hl++) {
                        float val = (acc[w][am][an][hl * 2 + cc] + bv_) * scl;
                        out[((size_t)(h * BB + mb[am][hl]) * NN + mn[am][hl]) * DHE + dh]
                            = __uint_as_float(f2tf(val));
                    }
            }
        }
    }
}

// ============================================================
// K2: QR banded GEMM -> pure store into g_r[x][i][j], j in [0, vlen).
// ============================================================
__global__ __launch_bounds__(256) void qr_kernel(const float* __restrict__ pos_k,
                                                 const int* __restrict__ vl)
{
    __shared__ uint32_t qs[64][68];
    __shared__ uint32_t ps[64][68];

    const int x = blockIdx.z;
    const int b = x & (BB - 1);
    const int vlen = vl[b];
    const int r0 = blockIdx.x * 64;
    const int i0 = blockIdx.y * 64;
    if (r0 + i0 + 126 - PCLIP < 0) return;
    if (r0 + i0 - PCLIP >= vlen) return;

    const int tid = threadIdx.x;
    const int lane = tid & 31, warp = tid >> 5;
    const int g = lane >> 2, t = lane & 3;
    const int wm = warp >> 1, wn = warp & 1;

    const float* qb = g_q + (size_t)x * NN * DHE;

    #pragma unroll
    for (int it = 0; it < 16; it++) {
        int idx = tid + it * 256;
        int r = idx >> 6, c = idx & 63;
        qs[r][c] = (i0 + r < NN) ? __float_as_uint(qb[(size_t)(i0 + r) * DHE + c]) : 0u;
        ps[r][c] = (r0 + r < RLEN) ? __float_as_uint(pos_k[(size_t)(r0 + r) * DHE + c]) : 0u;
    }
    __syncthreads();

    float acc[4][4];
    #pragma unroll
    for (int an = 0; an < 4; an++)
        #pragma unroll
        for (int e = 0; e < 4; e++) acc[an][e] = 0.f;

    const int ib = wm * 16;
    #pragma unroll
    for (int kk = 0; kk < 64; kk += 8) {
        uint32_t a0 = qs[ib + g][kk + t];
        uint32_t a1 = qs[ib + 8 + g][kk + t];
        uint32_t a2 = qs[ib + g][kk + t + 4];
        uint32_t a3 = qs[ib + 8 + g][kk + t + 4];
        #pragma unroll
        for (int an = 0; an < 4; an++) {
            int n = wn * 32 + an * 8 + g;
            uint32_t b0 = ps[n][kk + t];
            uint32_t b1 = ps[n][kk + t + 4];
            mma_tf32(acc[an], a0, a1, a2, a3, b0, b1);
        }
    }

    float* rrow = g_r + (size_t)x * NN * NN;
    #pragma unroll
    for (int an = 0; an < 4; an++) {
        int rr = r0 + wn * 32 + an * 8 + 2 * t;
        #pragma unroll
        for (int hl = 0; hl < 2; hl++) {
            int i = i0 + ib + g + hl * 8;
            if (i < NN) {
                #pragma unroll
                for (int cc = 0; cc < 2; cc++) {
                    int j = rr + cc + i - PCLIP;
                    if (j >= 0 && j < vlen)
                        rrow[(size_t)i * NN + j] = acc[an][hl * 2 + cc];
                }
            }
        }
    }
}

// ============================================================
// K3: flash attention: S = q·k^T + g_r, online softmax, O = P·v.
// ============================================================
__global__ __launch_bounds__(128) void flash_kernel(const int* __restrict__ vl)
{
    extern __shared__ uint32_t fsm[];
    uint32_t (*qs)[68] = (uint32_t(*)[68])fsm;
    uint32_t (*ks)[68] = (uint32_t(*)[68])(fsm + 64 * 68);
    uint32_t (*vs)[68] = (uint32_t(*)[68])(fsm + 2 * 64 * 68);
    uint32_t (*ps)[68] = (uint32_t(*)[68])(fsm + 3 * 64 * 68);

    const int x = blockIdx.y;
    const int b = x & (BB - 1);
    const int vlen = vl[b];
    const int i0 = blockIdx.x * 64;

    const int tid = threadIdx.x;
    const int lane = tid & 31, warp = tid >> 5;
    const int g = lane >> 2, t = lane & 3;
    const int ib = warp * 16;

    const float* qb = g_q + (size_t)x * NN * DHE;
    const float* kb = g_k + (size_t)x * NN * DHE;
    const float* vb = g_v + (size_t)x * NN * DHE;
    const float* rb = g_r + (size_t)x * NN * NN;

    #pragma unroll
    for (int it = 0; it < 8; it++) {
        int idx = tid + it * 128;
        int r = idx >> 4, c4 = (idx & 15) * 4;
        uint4 val = make_uint4(0u, 0u, 0u, 0u);
        if (i0 + r < NN) val = *(const uint4*)(qb + (size_t)(i0 + r) * DHE + c4);
        qs[r][c4] = val.x; qs[r][c4 + 1] = val.y; qs[r][c4 + 2] = val.z; qs[r][c4 + 3] = val.w;
    }

    const int irow0 = i0 + ib + g;
    const int irow1 = irow0 + 8;
    const bool iok0 = irow0 < NN, iok1 = irow1 < NN;

    float m0 = -1e30f, m1 = -1e30f, l0 = 0.f, l1 = 0.f;
    float oacc[8][4];
    #pragma unroll
    for (int fn = 0; fn < 8; fn++)
        #pragma unroll
        for (int e = 0; e < 4; e++) oacc[fn][e] = 0.f;

    for (int j0 = 0; j0 < vlen; j0 += 64) {
        __syncthreads();
        #pragma unroll
        for (int it = 0; it < 8; it++) {
            int idx = tid + it * 128;
            int r = idx >> 4, c4 = (idx & 15) * 4;
            uint4 kv = make_uint4(0u, 0u, 0u, 0u), vv = make_uint4(0u, 0u, 0u, 0u);
            if (j0 + r < NN) {
                kv = *(const uint4*)(kb + (size_t)(j0 + r) * DHE + c4);
                vv = *(const uint4*)(vb + (size_t)(j0 + r) * DHE + c4);
            }
            ks[r][c4] = kv.x; ks[r][c4 + 1] = kv.y; ks[r][c4 + 2] = kv.z; ks[r][c4 + 3] = kv.w;
            vs[r][c4] = vv.x; vs[r][c4 + 1] = vv.y; vs[r][c4 + 2] = vv.z; vs[r][c4 + 3] = vv.w;
        }
        __syncthreads();

        float sacc[8][4];
        #pragma unroll
        for (int fn = 0; fn < 8; fn++)
            #pragma unroll
            for (int e = 0; e < 4; e++) sacc[fn][e] = 0.f;

        #pragma unroll
        for (int kk = 0; kk < 64; kk += 8) {
            uint32_t a0 = qs[ib + g][kk + t];
            uint32_t a1 = qs[ib + 8 + g][kk + t];
            uint32_t a2 = qs[ib + g][kk + t + 4];
            uint32_t a3 = qs[ib + 8 + g][kk + t + 4];
            #pragma unroll
            for (int fn = 0; fn < 8; fn++) {
                int n = fn * 8 + g;
                mma_tf32(sacc[fn], a0, a1, a2, a3, ks[n][kk + t], ks[n][kk + t + 4]);
            }
        }

        float tm0 = -1e30f, tm1 = -1e30f;
        #pragma unroll
        for (int fn = 0; fn < 8; fn++) {
            int j = j0 + fn * 8 + 2 * t;
            float r00 = -1e30f, r01 = -1e30f, r10 = -1e30f, r11 = -1e30f;
            if (j < vlen) {
                if (j + 1 < vlen) {
                    if (iok0) { float2 rr = *(const float2*)(rb + (size_t)irow0 * NN + j); r00 = rr.x; r01 = rr.y; }
                    if (iok1) { float2 rr = *(const float2*)(rb + (size_t)irow1 * NN + j); r10 = rr.x; r11 = rr.y; }
                } else {
                    if (iok0) r00 = rb[(size_t)irow0 * NN + j];
                    if (iok1) r10 = rb[(size_t)irow1 * NN + j];
                }
            }
            sacc[fn][0] += r00; sacc[fn][1] += r01;
            sacc[fn][2] += r10; sacc[fn][3] += r11;
            tm0 = fmaxf(tm0, fmaxf(sacc[fn][0], sacc[fn][1]));
            tm1 = fmaxf(tm1, fmaxf(sacc[fn][2], sacc[fn][3]));
        }
        tm0 = fmaxf(tm0, __shfl_xor_sync(0xffffffffu, tm0, 1));
        tm0 = fmaxf(tm0, __shfl_xor_sync(0xffffffffu, tm0, 2));
        tm1 = fmaxf(tm1, __shfl_xor_sync(0xffffffffu, tm1, 1));
        tm1 = fmaxf(tm1, __shfl_xor_sync(0xffffffffu, tm1, 2));

        float mn0 = fmaxf(m0, tm0), mn1 = fmaxf(m1, tm1);
        float sc0 = __expf(m0 - mn0), sc1 = __expf(m1 - mn1);
        m0 = mn0; m1 = mn1;

        float tl0 = 0.f, tl1 = 0.f;
        #pragma unroll
        for (int fn = 0; fn < 8; fn++) {
            float p00 = __expf(sacc[fn][0] - mn0);
            float p01 = __expf(sacc[fn][1] - mn0);
            float p10 = __expf(sacc[fn][2] - mn1);
            float p11 = __expf(sacc[fn][3] - mn1);
            tl0 += p00 + p01; tl1 += p10 + p11;
            int c0 = fn * 8 + 2 * t;
            ps[ib + g][c0]         = f2tf(p00);
            ps[ib + g][c0 + 1]     = f2tf(p01);
            ps[ib + 8 + g][c0]     = f2tf(p10);
            ps[ib + 8 + g][c0 + 1] = f2tf(p11);
        }
        tl0 += __shfl_xor_sync(0xffffffffu, tl0, 1);
        tl0 += __shfl_xor_sync(0xffffffffu, tl0, 2);
        tl1 += __shfl_xor_sync(0xffffffffu, tl1, 1);
        tl1 += __shfl_xor_sync(0xffffffffu, tl1, 2);
        l0 = l0 * sc0 + tl0;
        l1 = l1 * sc1 + tl1;

        #pragma unroll
        for (int fn = 0; fn < 8; fn++) {
            oacc[fn][0] *= sc0; oacc[fn][1] *= sc0;
            oacc[fn][2] *= sc1; oacc[fn][3] *= sc1;
        }

        __syncwarp();

        #pragma unroll
        for (int kk = 0; kk < 64; kk += 8) {
            uint32_t a0 = ps[ib + g][kk + t];
            uint32_t a1 = ps[ib + 8 + g][kk + t];
            uint32_t a2 = ps[ib + g][kk + t + 4];
            uint32_t a3 = ps[ib + 8 + g][kk + t + 4];
            #pragma unroll
            for (int fn = 0; fn < 8; fn++) {
                int n = fn * 8 + g;
                mma_tf32(oacc[fn], a0, a1, a2, a3, vs[kk + t][n], vs[kk + t + 4][n]);
            }
        }
        __syncwarp();
    }

    float inv0 = 1.f / l0, inv1 = 1.f / l1;
    float* ob = g_ao + (size_t)x * NN * DHE;
    #pragma unroll
    for (int fn = 0; fn < 8; fn++) {
        int dh = fn * 8 + 2 * t;
        if (iok0) {
            float2 v;
            v.x = __uint_as_float(f2tf(oacc[fn][0] * inv0));
            v.y = __uint_as_float(f2tf(oacc[fn][1] * inv0));
            *(float2*)(ob + (size_t)irow0 * DHE + dh) = v;
        }
        if (iok1) {
            float2 v;
            v.x = __uint_as_float(f2tf(oacc[fn][2] * inv1));
            v.y = __uint_as_float(f2tf(oacc[fn][3] * inv1));
            *(float2*)(ob + (size_t)irow1 * DHE + dh) = v;
        }
    }
}

// ============================================================
// K5: output projection, cp.async 2-stage pipeline, K-panel 32.
// ============================================================
__global__ __launch_bounds__(256) void outproj_gemm(const float* __restrict__ W,
                                                    const float* __restrict__ bias,
                                                    const float* __restrict__ query)
{
    extern __shared__ uint32_t smbuf[];
    const uint32_t smem_base = (uint32_t)__cvta_generic_to_shared(smbuf);

    const int tid = threadIdx.x;
    const int lane = tid & 31, warp = tid >> 5;
    const int g = lane >> 2, t = lane & 3;
    const int wm = warp >> 1, wn = warp & 1;
    const int m0 = blockIdx.x * 128;
    const int n0 = blockIdx.y * 64;

    const int xrow[4] = { (tid) >> 3, (tid + 256) >> 3, (tid + 512) >> 3, (tid + 768) >> 3 };
    const int xcol4 = (tid & 7) * 4;
    const int brow[2] = { tid >> 4, (tid + 256) >> 4 };
    const int bcol4 = (tid & 15) * 4;

    // gather bases for the 4 A-rows this thread stages
    size_t pre[4];
    #pragma unroll
    for (int i = 0; i < 4; i++) {
        int m = m0 + xrow[i];
        int bb = m / NN, nn = m % NN;
        pre[i] = ((size_t)bb * NN + nn) * DHE;
    }

    float acc[2][4][4];
    #pragma unroll
    for (int am = 0; am < 2; am++)
        #pragma unroll
        for (int an = 0; an < 4; an++)
            #pragma unroll
            for (int e = 0; e < 4; e++) acc[am][an][e] = 0.f;

    auto load_panel = [&](int stage, int kt) {
        const int h = kt >> 1;
        const int dh0 = (kt & 1) * 32;
        const size_t hoff = (size_t)h * BB * NN * DHE;
        uint32_t xs = smem_base + (stage * X_TILE_U32) * 4;
        #pragma unroll
        for (int i = 0; i < 4; i++) {
            cp16(xs + (xrow[i] * XS_STRIDE + xcol4) * 4,
                 g_ao + hoff + pre[i] + dh0 + xcol4);
        }
        uint32_t bs = smem_base + (2 * X_TILE_U32 + stage * B_TILE_U32) * 4;
        #pragma unroll
        for (int i = 0; i < 2; i++) {
            cp16(bs + (brow[i] * BS_STRIDE + bcol4) * 4,
                 W + (size_t)(kt * 32 + brow[i]) * DD + n0 + bcol4);
        }
    };

    uint32_t (*Xsv)[XS_STRIDE] = (uint32_t(*)[XS_STRIDE])smbuf;
    uint32_t (*Bsv)[BS_STRIDE] = (uint32_t(*)[BS_STRIDE])(smbuf + 2 * X_TILE_U32);

    load_panel(0, 0);
    CP_COMMIT();

    const int NP = DD / 32;
    for (int kt = 0; kt < NP; kt++) {
        if (kt + 1 < NP) {
            load_panel((kt + 1) & 1, kt + 1);
            CP_COMMIT();
            CP_WAIT(1);
        } else {
            CP_WAIT(0);
        }
        __syncthreads();

        const int st = kt & 1;
        uint32_t (*Xs)[XS_STRIDE] = Xsv + st * 128;
        uint32_t (*Bs)[BS_STRIDE] = Bsv + st * 32;
        #pragma unroll
        for (int ks = 0; ks < 32; ks += 8) {
            uint32_t a[2][4];
            #pragma unroll
            for (int am = 0; am < 2; am++) {
                int row = wm * 32 + am * 16;
                a[am][0] = Xs[row + g][ks + t];
                a[am][1] = Xs[row + 8 + g][ks + t];
                a[am][2] = Xs[row + g][ks + t + 4];
                a[am][3] = Xs[row + 8 + g][ks + t + 4];
            }
            #pragma unroll
            for (int an = 0; an < 4; an++) {
                int n = wn * 32 + an * 8 + g;
                uint32_t b0 = Bs[ks + t][n];
                uint32_t b1 = Bs[ks + t + 4][n];
                mma_tf32(acc[0][an], a[0][0], a[0][1], a[0][2], a[0][3], b0, b1);
                mma_tf32(acc[1][an], a[1][0], a[1][1], a[1][2], a[1][3], b0, b1);
            }
        }
        __syncthreads();
    }

    #pragma unroll
    for (int an = 0; an < 4; an++) {
        int col = n0 + wn * 32 + an * 8 + 2 * t;
        #pragma unroll
        for (int cc = 0; cc < 2; cc++) {
            int e = col + cc;
            float bv_ = bias[e];
            #pragma unroll
            for (int am = 0; am < 2; am++)
                #pragma unroll
                for (int hl = 0; hl < 2; hl++) {
                    int m = m0 + wm * 32 + am * 16 + g + hl * 8;
                    g_o[(size_t)m * DD + e] =
                        acc[am][an][hl * 2 + cc] + bv_ + query[(size_t)m * DD + e];
                }
        }
    }
}

// ============================================================
// K6: LayerNorm over D=512 per row -> d_out
// ============================================================
__global__ __launch_bounds__(256) void ln_kernel(const float* __restrict__ gamma,
                                                 const float* __restrict__ beta,
                                                 float* __restrict__ out)
{
    const int m = blockIdx.x;
    const float* xr = g_o + (size_t)m * DD;
    const int tid = threadIdx.x;

    __shared__ float red[8];

    float x0 = xr[tid], x1 = xr[tid + 256];
    float s = x0 + x1;
    #pragma unroll
    for (int off = 16; off > 0; off >>= 1)
        s += __shfl_xor_sync(0xffffffff, s, off);
    if ((tid & 31) == 0) red[tid >> 5] = s;
    __syncthreads();
    float tot = 0.f;
    #pragma unroll
    for (int w = 0; w < 8; w++) tot += red[w];
    float mean = tot * (1.f / DD);

    float d0 = x0 - mean, d1 = x1 - mean;
    float ss = d0 * d0 + d1 * d1;
    #pragma unroll
    for (int off = 16; off > 0; off >>= 1)
        ss += __shfl_xor_sync(0xffffffff, ss, off);
    __syncthreads();
    if ((tid & 31) == 0) red[tid >> 5] = ss;
    __syncthreads();
    float tss = 0.f;
    #pragma unroll
    for (int w = 0; w < 8; w++) tss += red[w];
    float var = tss * (1.f / DD);
    float rstd = rsqrtf(var + 1e-7f);

    out[(size_t)m * DD + tid]       = gamma[tid]       * d0 * rstd + beta[tid];
    out[(size_t)m * DD + tid + 256] = gamma[tid + 256] * d1 * rstd + beta[tid + 256];
}

// ============================================================
extern "C" void kernel_launch(void* const* d_in, const int* in_sizes, int n_in,
                              void* d_out, int out_size)
{
    const float* query = (const float*)d_in[0];
    const float* Wq    = (const float*)d_in[1];
    const float* bq    = (const float*)d_in[2];
    const float* Wk    = (const float*)d_in[3];
    const float* bk    = (const float*)d_in[4];
    const float* Wv    = (const float*)d_in[5];
    const float* bv    = (const float*)d_in[6];
    const float* Wh    = (const float*)d_in[7];
    const float* bh    = (const float*)d_in[8];
    const float* pos_k = (const float*)d_in[9];
    const float* gamma = (const float*)d_in[10];
    const float* beta  = (const float*)d_in[11];
    const int*   vl    = (const int*)d_in[12];
    float* out = (float*)d_out;

    const int FLASH_SMEM = 4 * 64 * 68 * 4;                        // 69632 B
    const int QKV_SMEM   = (2 * X_TILE_U32 + 6 * B_TILE_U32) * 4;  // 89088 B
    const int OUT_SMEM   = (2 * X_TILE_U32 + 2 * B_TILE_U32) * 4;  // 54272 B

    static int smem_set = 0;
    if (!smem_set) {
        cudaFuncSetAttribute(flash_kernel,
                             cudaFuncAttributeMaxDynamicSharedMemorySize, FLASH_SMEM);
        cudaFuncSetAttribute(qkv_fused,
                             cudaFuncAttributeMaxDynamicSharedMemorySize, QKV_SMEM);
        cudaFuncSetAttribute(outproj_gemm,
                             cudaFuncAttributeMaxDynamicSharedMemorySize, OUT_SMEM);
        smem_set = 1;
    }

    qkv_fused<<<dim3(BN / 128, DD / 64), 256, QKV_SMEM>>>(query, Wq, bq, Wk, bk, Wv, bv);

    qr_kernel<<<dim3(17, 9, HB), 256>>>(pos_k, vl);

    flash_kernel<<<dim3(9, HB), 128, FLASH_SMEM>>>(vl);

    outproj_gemm<<<dim3(BN / 128, DD / 64), 256, OUT_SMEM>>>(Wh, bh, query);
    ln_kernel<<<BN, 256>>>(gamma, beta, out);
}

// round 5
// speedup vs baseline: 4.5050x; 1.1701x over previous
#include <cuda_runtime.h>
#include <cstdint>
#include <math.h>

#define BB 32
#define NN 540
#define DD 512
#define HH 8
#define DHE 64
#define HB (HH*BB)          // 256
#define BN (BB*NN)          // 17280
#define PCLIP 539
#define RLEN (2*PCLIP+1)    // 1079

// -------- scratch (device globals) --------
__device__ float g_q[(size_t)HB*NN*DHE];   // tf32 bits, q pre-scaled by 0.125
__device__ float g_k[(size_t)HB*NN*DHE];   // tf32 bits
__device__ float g_v[(size_t)HB*NN*DHE];   // tf32 bits
__device__ float g_ao[(size_t)HB*NN*DHE];  // attn@v, tf32 bits, head-major
__device__ float g_o[(size_t)BN*DD];       // pre-LN (fp32)

// -------- helpers --------
__device__ __forceinline__ uint32_t f2tf(float f) {
    uint32_t u;
    asm("cvt.rna.tf32.f32 %0, %1;" : "=r"(u) : "f"(f));
    return u;
}

__device__ __forceinline__ void mma_tf32(float c[4],
                                         uint32_t a0, uint32_t a1, uint32_t a2, uint32_t a3,
                                         uint32_t b0, uint32_t b1) {
    asm volatile(
        "mma.sync.aligned.m16n8k8.row.col.f32.tf32.tf32.f32 "
        "{%0,%1,%2,%3}, {%4,%5,%6,%7}, {%8,%9}, {%0,%1,%2,%3};\n"
        : "+f"(c[0]), "+f"(c[1]), "+f"(c[2]), "+f"(c[3])
        : "r"(a0), "r"(a1), "r"(a2), "r"(a3), "r"(b0), "r"(b1));
}

__device__ __forceinline__ void cp16(uint32_t smem_u32_addr, const void* gptr) {
    asm volatile("cp.async.cg.shared.global [%0], [%1], 16;\n"
                 :: "r"(smem_u32_addr), "l"(gptr));
}
#define CP_COMMIT() asm volatile("cp.async.commit_group;\n" ::)
#define CP_WAIT(n)  asm volatile("cp.async.wait_group %0;\n" :: "n"(n))

// smem tiling constants for pipelined GEMMs
#define XS_STRIDE 36
#define X_TILE_U32 (128*XS_STRIDE)     // 4608
#define BS_STRIDE 68
#define B_TILE_U32 (32*BS_STRIDE)      // 2176
#define OBS_STRIDE 132
#define OB_TILE_U32 (32*OBS_STRIDE)    // 4224

// ============================================================
// K1: fused QKV projection, tf32 mma, cp.async 2-stage pipeline.
// Block tile 128x64 (x3 weights), K-panel 32, 8 warps.
// ============================================================
__global__ __launch_bounds__(256) void qkv_fused(const float* __restrict__ X,
                                                 const float* __restrict__ Wq, const float* __restrict__ bq,
                                                 const float* __restrict__ Wk, const float* __restrict__ bk,
                                                 const float* __restrict__ Wv, const float* __restrict__ bv)
{
    extern __shared__ uint32_t smbuf[];
    const uint32_t smem_base = (uint32_t)__cvta_generic_to_shared(smbuf);

    const int tid = threadIdx.x;
    const int lane = tid & 31, warp = tid >> 5;
    const int g = lane >> 2, t = lane & 3;
    const int wm = warp >> 1, wn = warp & 1;
    const int m0 = blockIdx.x * 128;
    const int n0 = blockIdx.y * 64;

    const float* Ws[3] = {Wq, Wk, Wv};

    const int xrow[4] = { (tid) >> 3, (tid + 256) >> 3, (tid + 512) >> 3, (tid + 768) >> 3 };
    const int xcol4 = (tid & 7) * 4;
    const int brow[2] = { tid >> 4, (tid + 256) >> 4 };
    const int bcol4 = (tid & 15) * 4;

    float acc[3][2][4][4];
    #pragma unroll
    for (int w = 0; w < 3; w++)
        #pragma unroll
        for (int am = 0; am < 2; am++)
            #pragma unroll
            for (int an = 0; an < 4; an++)
                #pragma unroll
                for (int e = 0; e < 4; e++) acc[w][am][an][e] = 0.f;

    auto load_panel = [&](int stage, int k0) {
        uint32_t xs = smem_base + (stage * X_TILE_U32) * 4;
        #pragma unroll
        for (int i = 0; i < 4; i++) {
            cp16(xs + (xrow[i] * XS_STRIDE + xcol4) * 4,
                 X + (size_t)(m0 + xrow[i]) * DD + k0 + xcol4);
        }
        #pragma unroll
        for (int w = 0; w < 3; w++) {
            uint32_t bs = smem_base + (2 * X_TILE_U32 + (stage * 3 + w) * B_TILE_U32) * 4;
            #pragma unroll
            for (int i = 0; i < 2; i++) {
                cp16(bs + (brow[i] * BS_STRIDE + bcol4) * 4,
                     Ws[w] + (size_t)(k0 + brow[i]) * DD + n0 + bcol4);
            }
        }
    };

    uint32_t (*Xsv)[XS_STRIDE] = (uint32_t(*)[XS_STRIDE])smbuf;
    uint32_t (*Bsv)[BS_STRIDE] = (uint32_t(*)[BS_STRIDE])(smbuf + 2 * X_TILE_U32);

    load_panel(0, 0);
    CP_COMMIT();

    const int NP = DD / 32;
    for (int kt = 0; kt < NP; kt++) {
        if (kt + 1 < NP) {
            load_panel((kt + 1) & 1, (kt + 1) * 32);
            CP_COMMIT();
            CP_WAIT(1);
        } else {
            CP_WAIT(0);
        }
        __syncthreads();

        const int st = kt & 1;
        uint32_t (*Xs)[XS_STRIDE] = Xsv + st * 128;
        #pragma unroll
        for (int ks = 0; ks < 32; ks += 8) {
            uint32_t a[2][4];
            #pragma unroll
            for (int am = 0; am < 2; am++) {
                int row = wm * 32 + am * 16;
                a[am][0] = Xs[row + g][ks + t];
                a[am][1] = Xs[row + 8 + g][ks + t];
                a[am][2] = Xs[row + g][ks + t + 4];
                a[am][3] = Xs[row + 8 + g][ks + t + 4];
            }
            #pragma unroll
            for (int w = 0; w < 3; w++) {
                uint32_t (*Bs)[BS_STRIDE] = Bsv + (st * 3 + w) * 32;
                #pragma unroll
                for (int an = 0; an < 4; an++) {
                    int n = wn * 32 + an * 8 + g;
                    uint32_t b0 = Bs[ks + t][n];
                    uint32_t b1 = Bs[ks + t + 4][n];
                    mma_tf32(acc[w][0][an], a[0][0], a[0][1], a[0][2], a[0][3], b0, b1);
                    mma_tf32(acc[w][1][an], a[1][0], a[1][1], a[1][2], a[1][3], b0, b1);
                }
            }
        }
        __syncthreads();
    }

    int mb[2][2], mn[2][2];
    #pragma unroll
    for (int am = 0; am < 2; am++)
        #pragma unroll
        for (int hl = 0; hl < 2; hl++) {
            int m = m0 + wm * 32 + am * 16 + g + hl * 8;
            mb[am][hl] = m / NN;
            mn[am][hl] = m % NN;
        }

    const float* biases[3] = {bq, bk, bv};
    #pragma unroll
    for (int w = 0; w < 3; w++) {
        float* out = (w == 0) ? g_q : (w == 1) ? g_k : g_v;
        const float* bias = biases[w];
        float scl = (w == 0) ? 0.125f : 1.0f;
        #pragma unroll
        for (int an = 0; an < 4; an++) {
            int col = n0 + wn * 32 + an * 8 + 2 * t;
            #pragma unroll
            for (int cc = 0; cc < 2; cc++) {
                int e = col + cc;
                int h = e >> 6, dh = e & 63;
                float bv_ = bias[e];
                #pragma unroll
                for (int am = 0; am < 2; am++)
                    #pragma unroll
                    for (int hl = 0; hl < 2; hl++) {
                        float val = (acc[w][am][an][hl * 2 + cc] + bv_) * scl;
                        out[((size_t)(h * BB + mb[am][hl]) * NN + mn[am][hl]) * DHE + dh]
                            = __uint_as_float(f2tf(val));
                    }
            }
        }
    }
}

// ============================================================
// K3: flash attention with fused relative-position bias.
// Per (i-tile 64, j-tile 64): Rlo/Rhi = q @ posSlice^T via mma (staged in
// smem), S = q·k^T + gather(R), online softmax, O += P·v.
// 128 threads (4 warps x 16 rows). smem: 6 x 64x68 u32 = 104448 B.
// ============================================================
__global__ __launch_bounds__(128) void flash_kernel(const float* __restrict__ pos_k,
                                                    const int* __restrict__ vl)
{
    extern __shared__ uint32_t fsm[];
    uint32_t (*qs)[68] = (uint32_t(*)[68])fsm;
    uint32_t (*ks)[68] = (uint32_t(*)[68])(fsm + 4352);
    uint32_t (*vs)[68] = (uint32_t(*)[68])(fsm + 2 * 4352);
    uint32_t (*ps)[68] = (uint32_t(*)[68])(fsm + 3 * 4352);
    uint32_t (*pl)[68] = (uint32_t(*)[68])(fsm + 4 * 4352);
    uint32_t (*ph)[68] = (uint32_t(*)[68])(fsm + 5 * 4352);
    float (*plf)[68] = (float(*)[68])pl;
    float (*phf)[68] = (float(*)[68])ph;

    const int x = blockIdx.y;
    const int b = x & (BB - 1);
    const int vlen = vl[b];
    const int i0 = blockIdx.x * 64;

    const int tid = threadIdx.x;
    const int lane = tid & 31, warp = tid >> 5;
    const int g = lane >> 2, t = lane & 3;
    const int ib = warp * 16;

    const float* qb = g_q + (size_t)x * NN * DHE;
    const float* kb = g_k + (size_t)x * NN * DHE;
    const float* vb = g_v + (size_t)x * NN * DHE;

    // load q tile once (tf32 bits)
    #pragma unroll
    for (int it = 0; it < 8; it++) {
        int idx = tid + it * 128;
        int r = idx >> 4, c4 = (idx & 15) * 4;
        uint4 val = make_uint4(0u, 0u, 0u, 0u);
        if (i0 + r < NN) val = *(const uint4*)(qb + (size_t)(i0 + r) * DHE + c4);
        qs[r][c4] = val.x; qs[r][c4 + 1] = val.y; qs[r][c4 + 2] = val.z; qs[r][c4 + 3] = val.w;
    }

    const int irow0 = i0 + ib + g;
    const int irow1 = irow0 + 8;
    const bool iok0 = irow0 < NN, iok1 = irow1 < NN;
    const int ii0 = ib + g, ii1 = ib + g + 8;

    float m0 = -1e30f, m1 = -1e30f, l0 = 0.f, l1 = 0.f;
    float oacc[8][4];
    #pragma unroll
    for (int fn = 0; fn < 8; fn++)
        #pragma unroll
        for (int e = 0; e < 4; e++) oacc[fn][e] = 0.f;

    for (int j0 = 0; j0 < vlen; j0 += 64) {
        const int base = j0 - i0 + PCLIP;
        __syncthreads();
        // load k/v tiles and pos slices
        #pragma unroll
        for (int it = 0; it < 8; it++) {
            int idx = tid + it * 128;
            int r = idx >> 4, c4 = (idx & 15) * 4;
            uint4 kv = make_uint4(0u, 0u, 0u, 0u), vv = make_uint4(0u, 0u, 0u, 0u);
            if (j0 + r < NN) {
                kv = *(const uint4*)(kb + (size_t)(j0 + r) * DHE + c4);
                vv = *(const uint4*)(vb + (size_t)(j0 + r) * DHE + c4);
            }
            ks[r][c4] = kv.x; ks[r][c4 + 1] = kv.y; ks[r][c4 + 2] = kv.z; ks[r][c4 + 3] = kv.w;
            vs[r][c4] = vv.x; vs[r][c4 + 1] = vv.y; vs[r][c4 + 2] = vv.z; vs[r][c4 + 3] = vv.w;
            int rlo = base - 63 + r;
            uint4 pv = make_uint4(0u, 0u, 0u, 0u);
            if (rlo >= 0 && rlo < RLEN)
                pv = *(const uint4*)(pos_k + (size_t)rlo * DHE + c4);
            pl[r][c4] = pv.x; pl[r][c4 + 1] = pv.y; pl[r][c4 + 2] = pv.z; pl[r][c4 + 3] = pv.w;
            int rhi = base + r;
            uint4 pw = make_uint4(0u, 0u, 0u, 0u);
            if (rhi >= 0 && rhi < RLEN)
                pw = *(const uint4*)(pos_k + (size_t)rhi * DHE + c4);
            ph[r][c4] = pw.x; ph[r][c4 + 1] = pw.y; ph[r][c4 + 2] = pw.z; ph[r][c4 + 3] = pw.w;
        }
        __syncthreads();

        // ---- Rlo = q · Plo^T ----
        float tacc[8][4];
        #pragma unroll
        for (int fn = 0; fn < 8; fn++)
            #pragma unroll
            for (int e = 0; e < 4; e++) tacc[fn][e] = 0.f;
        #pragma unroll
        for (int kk = 0; kk < 64; kk += 8) {
            uint32_t a0 = qs[ib + g][kk + t];
            uint32_t a1 = qs[ib + 8 + g][kk + t];
            uint32_t a2 = qs[ib + g][kk + t + 4];
            uint32_t a3 = qs[ib + 8 + g][kk + t + 4];
            #pragma unroll
            for (int fn = 0; fn < 8; fn++) {
                int n = fn * 8 + g;
                mma_tf32(tacc[fn], a0, a1, a2, a3, pl[n][kk + t], pl[n][kk + t + 4]);
            }
        }
        __syncthreads();   // all warps finished reading pl
        #pragma unroll
        for (int fn = 0; fn < 8; fn++) {
            int c0 = fn * 8 + 2 * t;
            plf[ii0][c0]     = tacc[fn][0]; plf[ii0][c0 + 1] = tacc[fn][1];
            plf[ii1][c0]     = tacc[fn][2]; plf[ii1][c0 + 1] = tacc[fn][3];
        }

        // ---- Rhi = q · Phi^T ----
        #pragma unroll
        for (int fn = 0; fn < 8; fn++)
            #pragma unroll
            for (int e = 0; e < 4; e++) tacc[fn][e] = 0.f;
        #pragma unroll
        for (int kk = 0; kk < 64; kk += 8) {
            uint32_t a0 = qs[ib + g][kk + t];
            uint32_t a1 = qs[ib + 8 + g][kk + t];
            uint32_t a2 = qs[ib + g][kk + t + 4];
            uint32_t a3 = qs[ib + 8 + g][kk + t + 4];
            #pragma unroll
            for (int fn = 0; fn < 8; fn++) {
                int n = fn * 8 + g;
                mma_tf32(tacc[fn], a0, a1, a2, a3, ph[n][kk + t], ph[n][kk + t + 4]);
            }
        }
        __syncthreads();   // all warps finished reading ph
        #pragma unroll
        for (int fn = 0; fn < 8; fn++) {
            int c0 = fn * 8 + 2 * t;
            phf[ii0][c0]     = tacc[fn][0]; phf[ii0][c0 + 1] = tacc[fn][1];
            phf[ii1][c0]     = tacc[fn][2]; phf[ii1][c0 + 1] = tacc[fn][3];
        }
        __syncwarp();      // own-warp rows: cross-thread visibility within warp

        // ---- S = q · k^T ----
        float sacc[8][4];
        #pragma unroll
        for (int fn = 0; fn < 8; fn++)
            #pragma unroll
            for (int e = 0; e < 4; e++) sacc[fn][e] = 0.f;
        #pragma unroll
        for (int kk = 0; kk < 64; kk += 8) {
            uint32_t a0 = qs[ib + g][kk + t];
            uint32_t a1 = qs[ib + 8 + g][kk + t];
            uint32_t a2 = qs[ib + g][kk + t + 4];
            uint32_t a3 = qs[ib + 8 + g][kk + t + 4];
            #pragma unroll
            for (int fn = 0; fn < 8; fn++) {
                int n = fn * 8 + g;
                mma_tf32(sacc[fn], a0, a1, a2, a3, ks[n][kk + t], ks[n][kk + t + 4]);
            }
        }

        // ---- gather R from smem, add, mask; tile row max ----
        float tm0 = -1e30f, tm1 = -1e30f;
        #pragma unroll
        for (int fn = 0; fn < 8; fn++) {
            int jj = fn * 8 + 2 * t;
            int j = j0 + jj;
            int d00 = jj - ii0;          // row irow0, col j
            int d10 = jj - ii1;          // row irow1, col j
            float r00 = (d00 >= 0) ? phf[ii0][d00] : plf[ii0][d00 + 63];
            float r01 = (d00 + 1 >= 0) ? phf[ii0][d00 + 1] : plf[ii0][d00 + 64];
            float r10 = (d10 >= 0) ? phf[ii1][d10] : plf[ii1][d10 + 63];
            float r11 = (d10 + 1 >= 0) ? phf[ii1][d10 + 1] : plf[ii1][d10 + 64];
            sacc[fn][0] = (j < vlen)     ? sacc[fn][0] + r00 : -1e30f;
            sacc[fn][1] = (j + 1 < vlen) ? sacc[fn][1] + r01 : -1e30f;
            sacc[fn][2] = (j < vlen)     ? sacc[fn][2] + r10 : -1e30f;
            sacc[fn][3] = (j + 1 < vlen) ? sacc[fn][3] + r11 : -1e30f;
            tm0 = fmaxf(tm0, fmaxf(sacc[fn][0], sacc[fn][1]));
            tm1 = fmaxf(tm1, fmaxf(sacc[fn][2], sacc[fn][3]));
        }
        tm0 = fmaxf(tm0, __shfl_xor_sync(0xffffffffu, tm0, 1));
        tm0 = fmaxf(tm0, __shfl_xor_sync(0xffffffffu, tm0, 2));
        tm1 = fmaxf(tm1, __shfl_xor_sync(0xffffffffu, tm1, 1));
        tm1 = fmaxf(tm1, __shfl_xor_sync(0xffffffffu, tm1, 2));

        float mn0 = fmaxf(m0, tm0), mn1 = fmaxf(m1, tm1);
        float sc0 = __expf(m0 - mn0), sc1 = __expf(m1 - mn1);
        m0 = mn0; m1 = mn1;

        float tl0 = 0.f, tl1 = 0.f;
        #pragma unroll
        for (int fn = 0; fn < 8; fn++) {
            float p00 = __expf(sacc[fn][0] - mn0);
            float p01 = __expf(sacc[fn][1] - mn0);
            float p10 = __expf(sacc[fn][2] - mn1);
            float p11 = __expf(sacc[fn][3] - mn1);
            tl0 += p00 + p01; tl1 += p10 + p11;
            int c0 = fn * 8 + 2 * t;
            ps[ii0][c0]     = f2tf(p00);
            ps[ii0][c0 + 1] = f2tf(p01);
            ps[ii1][c0]     = f2tf(p10);
            ps[ii1][c0 + 1] = f2tf(p11);
        }
        tl0 += __shfl_xor_sync(0xffffffffu, tl0, 1);
        tl0 += __shfl_xor_sync(0xffffffffu, tl0, 2);
        tl1 += __shfl_xor_sync(0xffffffffu, tl1, 1);
        tl1 += __shfl_xor_sync(0xffffffffu, tl1, 2);
        l0 = l0 * sc0 + tl0;
        l1 = l1 * sc1 + tl1;

        #pragma unroll
        for (int fn = 0; fn < 8; fn++) {
            oacc[fn][0] *= sc0; oacc[fn][1] *= sc0;
            oacc[fn][2] *= sc1; oacc[fn][3] *= sc1;
        }

        __syncwarp();

        // ---- O += P · V ----
        #pragma unroll
        for (int kk = 0; kk < 64; kk += 8) {
            uint32_t a0 = ps[ib + g][kk + t];
            uint32_t a1 = ps[ib + 8 + g][kk + t];
            uint32_t a2 = ps[ib + g][kk + t + 4];
            uint32_t a3 = ps[ib + 8 + g][kk + t + 4];
            #pragma unroll
            for (int fn = 0; fn < 8; fn++) {
                int n = fn * 8 + g;
                mma_tf32(oacc[fn], a0, a1, a2, a3, vs[kk + t][n], vs[kk + t + 4][n]);
            }
        }
        __syncwarp();
    }

    float inv0 = 1.f / l0, inv1 = 1.f / l1;
    float* ob = g_ao + (size_t)x * NN * DHE;
    #pragma unroll
    for (int fn = 0; fn < 8; fn++) {
        int dh = fn * 8 + 2 * t;
        if (iok0) {
            float2 v;
            v.x = __uint_as_float(f2tf(oacc[fn][0] * inv0));
            v.y = __uint_as_float(f2tf(oacc[fn][1] * inv0));
            *(float2*)(ob + (size_t)irow0 * DHE + dh) = v;
        }
        if (iok1) {
            float2 v;
            v.x = __uint_as_float(f2tf(oacc[fn][2] * inv1));
            v.y = __uint_as_float(f2tf(oacc[fn][3] * inv1));
            *(float2*)(ob + (size_t)irow1 * DHE + dh) = v;
        }
    }
}

// ============================================================
// K5: output projection, cp.async 2-stage pipeline, block tile 128x128,
// K-panel 32, warp tile 32x64 (8 warps: 4m x 2n).
// ============================================================
__global__ __launch_bounds__(256) void outproj_gemm(const float* __restrict__ W,
                                                    const float* __restrict__ bias,
                                                    const float* __restrict__ query)
{
    extern __shared__ uint32_t smbuf[];
    const uint32_t smem_base = (uint32_t)__cvta_generic_to_shared(smbuf);

    const int tid = threadIdx.x;
    const int lane = tid & 31, warp = tid >> 5;
    const int g = lane >> 2, t = lane & 3;
    const int wm = warp >> 1, wn = warp & 1;
    const int m0 = blockIdx.x * 128;
    const int n0 = blockIdx.y * 128;

    const int xrow[4] = { (tid) >> 3, (tid + 256) >> 3, (tid + 512) >> 3, (tid + 768) >> 3 };
    const int xcol4 = (tid & 7) * 4;
    const int brow[4] = { tid >> 5, (tid + 256) >> 5, (tid + 512) >> 5, (tid + 768) >> 5 };
    const int bcol4 = (tid & 31) * 4;

    size_t pre[4];
    #pragma unroll
    for (int i = 0; i < 4; i++) {
        int m = m0 + xrow[i];
        int bb = m / NN, nn = m % NN;
        pre[i] = ((size_t)bb * NN + nn) * DHE;
    }

    float acc[2][8][4];
    #pragma unroll
    for (int am = 0; am < 2; am++)
        #pragma unroll
        for (int an = 0; an < 8; an++)
            #pragma unroll
            for (int e = 0; e < 4; e++) acc[am][an][e] = 0.f;

    auto load_panel = [&](int stage, int kt) {
        const int h = kt >> 1;
        const int dh0 = (kt & 1) * 32;
        const size_t hoff = (size_t)h * BB * NN * DHE;
        uint32_t xs = smem_base + (stage * X_TILE_U32) * 4;
        #pragma unroll
        for (int i = 0; i < 4; i++) {
            cp16(xs + (xrow[i] * XS_STRIDE + xcol4) * 4,
                 g_ao + hoff + pre[i] + dh0 + xcol4);
        }
        uint32_t bs = smem_base + (2 * X_TILE_U32 + stage * OB_TILE_U32) * 4;
        #pragma unroll
        for (int i = 0; i < 4; i++) {
            cp16(bs + (brow[i] * OBS_STRIDE + bcol4) * 4,
                 W + (size_t)(kt * 32 + brow[i]) * DD + n0 + bcol4);
        }
    };

    uint32_t (*Xsv)[XS_STRIDE] = (uint32_t(*)[XS_STRIDE])smbuf;
    uint32_t (*Bsv)[OBS_STRIDE] = (uint32_t(*)[OBS_STRIDE])(smbuf + 2 * X_TILE_U32);

    load_panel(0, 0);
    CP_COMMIT();

    const int NP = DD / 32;
    for (int kt = 0; kt < NP; kt++) {
        if (kt + 1 < NP) {
            load_panel((kt + 1) & 1, kt + 1);
            CP_COMMIT();
            CP_WAIT(1);
        } else {
            CP_WAIT(0);
        }
        __syncthreads();

        const int st = kt & 1;
        uint32_t (*Xs)[XS_STRIDE] = Xsv + st * 128;
        uint32_t (*Bs)[OBS_STRIDE] = Bsv + st * 32;
        #pragma unroll
        for (int ks = 0; ks < 32; ks += 8) {
            uint32_t a[2][4];
            #pragma unroll
            for (int am = 0; am < 2; am++) {
                int row = wm * 32 + am * 16;
                a[am][0] = Xs[row + g][ks + t];
                a[am][1] = Xs[row + 8 + g][ks + t];
                a[am][2] = Xs[row + g][ks + t + 4];
                a[am][3] = Xs[row + 8 + g][ks + t + 4];
            }
            #pragma unroll
            for (int an = 0; an < 8; an++) {
                int n = wn * 64 + an * 8 + g;
                uint32_t b0 = Bs[ks + t][n];
                uint32_t b1 = Bs[ks + t + 4][n];
                mma_tf32(acc[0][an], a[0][0], a[0][1], a[0][2], a[0][3], b0, b1);
                mma_tf32(acc[1][an], a[1][0], a[1][1], a[1][2], a[1][3], b0, b1);
            }
        }
        __syncthreads();
    }

    #pragma unroll
    for (int an = 0; an < 8; an++) {
        int col = n0 + wn * 64 + an * 8 + 2 * t;
        #pragma unroll
        for (int cc = 0; cc < 2; cc++) {
            int e = col + cc;
            float bv_ = bias[e];
            #pragma unroll
            for (int am = 0; am < 2; am++)
                #pragma unroll
                for (int hl = 0; hl < 2; hl++) {
                    int m = m0 + wm * 32 + am * 16 + g + hl * 8;
                    g_o[(size_t)m * DD + e] =
                        acc[am][an][hl * 2 + cc] + bv_ + query[(size_t)m * DD + e];
                }
        }
    }
}

// ============================================================
// K6: LayerNorm over D=512 per row -> d_out
// ============================================================
__global__ __launch_bounds__(256) void ln_kernel(const float* __restrict__ gamma,
                                                 const float* __restrict__ beta,
                                                 float* __restrict__ out)
{
    const int m = blockIdx.x;
    const float* xr = g_o + (size_t)m * DD;
    const int tid = threadIdx.x;

    __shared__ float red[8];

    float x0 = xr[tid], x1 = xr[tid + 256];
    float s = x0 + x1;
    #pragma unroll
    for (int off = 16; off > 0; off >>= 1)
        s += __shfl_xor_sync(0xffffffff, s, off);
    if ((tid & 31) == 0) red[tid >> 5] = s;
    __syncthreads();
    float tot = 0.f;
    #pragma unroll
    for (int w = 0; w < 8; w++) tot += red[w];
    float mean = tot * (1.f / DD);

    float d0 = x0 - mean, d1 = x1 - mean;
    float ss = d0 * d0 + d1 * d1;
    #pragma unroll
    for (int off = 16; off > 0; off >>= 1)
        ss += __shfl_xor_sync(0xffffffff, ss, off);
    __syncthreads();
    if ((tid & 31) == 0) red[tid >> 5] = ss;
    __syncthreads();
    float tss = 0.f;
    #pragma unroll
    for (int w = 0; w < 8; w++) tss += red[w];
    float var = tss * (1.f / DD);
    float rstd = rsqrtf(var + 1e-7f);

    out[(size_t)m * DD + tid]       = gamma[tid]       * d0 * rstd + beta[tid];
    out[(size_t)m * DD + tid + 256] = gamma[tid + 256] * d1 * rstd + beta[tid + 256];
}

// ============================================================
extern "C" void kernel_launch(void* const* d_in, const int* in_sizes, int n_in,
                              void* d_out, int out_size)
{
    const float* query = (const float*)d_in[0];
    const float* Wq    = (const float*)d_in[1];
    const float* bq    = (const float*)d_in[2];
    const float* Wk    = (const float*)d_in[3];
    const float* bk    = (const float*)d_in[4];
    const float* Wv    = (const float*)d_in[5];
    const float* bv    = (const float*)d_in[6];
    const float* Wh    = (const float*)d_in[7];
    const float* bh    = (const float*)d_in[8];
    const float* pos_k = (const float*)d_in[9];
    const float* gamma = (const float*)d_in[10];
    const float* beta  = (const float*)d_in[11];
    const int*   vl    = (const int*)d_in[12];
    float* out = (float*)d_out;

    const int FLASH_SMEM = 6 * 64 * 68 * 4;                         // 104448 B
    const int QKV_SMEM   = (2 * X_TILE_U32 + 6 * B_TILE_U32) * 4;   // 89088 B
    const int OUT_SMEM   = (2 * X_TILE_U32 + 2 * OB_TILE_U32) * 4;  // 70656 B

    static int smem_set = 0;
    if (!smem_set) {
        cudaFuncSetAttribute(flash_kernel,
                             cudaFuncAttributeMaxDynamicSharedMemorySize, FLASH_SMEM);
        cudaFuncSetAttribute(qkv_fused,
                             cudaFuncAttributeMaxDynamicSharedMemorySize, QKV_SMEM);
        cudaFuncSetAttribute(outproj_gemm,
                             cudaFuncAttributeMaxDynamicSharedMemorySize, OUT_SMEM);
        smem_set = 1;
    }

    qkv_fused<<<dim3(BN / 128, DD / 64), 256, QKV_SMEM>>>(query, Wq, bq, Wk, bk, Wv, bv);

    flash_kernel<<<dim3(9, HB), 128, FLASH_SMEM>>>(pos_k, vl);

    outproj_gemm<<<dim3(BN / 128, DD / 128), 256, OUT_SMEM>>>(Wh, bh, query);
    ln_kernel<<<BN, 256>>>(gamma, beta, out);
}

// round 6
// speedup vs baseline: 4.7452x; 1.0533x over previous
#include <cuda_runtime.h>
#include <cstdint>
#include <math.h>

#define BB 32
#define NN 540
#define DD 512
#define HH 8
#define DHE 64
#define HB (HH*BB)          // 256
#define BN (BB*NN)          // 17280
#define PCLIP 539
#define RLEN (2*PCLIP+1)    // 1079

// -------- scratch (device globals) --------
__device__ float g_q[(size_t)HB*NN*DHE];   // tf32 bits, q pre-scaled by 0.125
__device__ float g_k[(size_t)HB*NN*DHE];   // tf32 bits
__device__ float g_v[(size_t)HB*NN*DHE];   // tf32 bits
__device__ float g_ao[(size_t)HB*NN*DHE];  // attn@v, tf32 bits, head-major
__device__ float g_o[(size_t)BN*DD];       // pre-LN (fp32)

// -------- helpers --------
__device__ __forceinline__ uint32_t f2tf(float f) {
    uint32_t u;
    asm("cvt.rna.tf32.f32 %0, %1;" : "=r"(u) : "f"(f));
    return u;
}

__device__ __forceinline__ void mma_tf32(float c[4],
                                         uint32_t a0, uint32_t a1, uint32_t a2, uint32_t a3,
                                         uint32_t b0, uint32_t b1) {
    asm volatile(
        "mma.sync.aligned.m16n8k8.row.col.f32.tf32.tf32.f32 "
        "{%0,%1,%2,%3}, {%4,%5,%6,%7}, {%8,%9}, {%0,%1,%2,%3};\n"
        : "+f"(c[0]), "+f"(c[1]), "+f"(c[2]), "+f"(c[3])
        : "r"(a0), "r"(a1), "r"(a2), "r"(a3), "r"(b0), "r"(b1));
}

__device__ __forceinline__ void cp16(uint32_t smem_u32_addr, const void* gptr) {
    asm volatile("cp.async.cg.shared.global [%0], [%1], 16;\n"
                 :: "r"(smem_u32_addr), "l"(gptr));
}
#define CP_COMMIT() asm volatile("cp.async.commit_group;\n" ::)
#define CP_WAIT(n)  asm volatile("cp.async.wait_group %0;\n" :: "n"(n))

// smem tiling constants for pipelined GEMMs
#define XS_STRIDE 36
#define X_TILE_U32 (128*XS_STRIDE)     // 4608
#define BS_STRIDE 68
#define B_TILE_U32 (32*BS_STRIDE)      // 2176
#define OBS_STRIDE 132
#define OB_TILE_U32 (32*OBS_STRIDE)    // 4224

// ============================================================
// K1: fused QKV projection, tf32 mma, cp.async 2-stage pipeline.
// ============================================================
__global__ __launch_bounds__(256) void qkv_fused(const float* __restrict__ X,
                                                 const float* __restrict__ Wq, const float* __restrict__ bq,
                                                 const float* __restrict__ Wk, const float* __restrict__ bk,
                                                 const float* __restrict__ Wv, const float* __restrict__ bv)
{
    extern __shared__ uint32_t smbuf[];
    const uint32_t smem_base = (uint32_t)__cvta_generic_to_shared(smbuf);

    const int tid = threadIdx.x;
    const int lane = tid & 31, warp = tid >> 5;
    const int g = lane >> 2, t = lane & 3;
    const int wm = warp >> 1, wn = warp & 1;
    const int m0 = blockIdx.x * 128;
    const int n0 = blockIdx.y * 64;

    const float* Ws[3] = {Wq, Wk, Wv};

    const int xrow[4] = { (tid) >> 3, (tid + 256) >> 3, (tid + 512) >> 3, (tid + 768) >> 3 };
    const int xcol4 = (tid & 7) * 4;
    const int brow[2] = { tid >> 4, (tid + 256) >> 4 };
    const int bcol4 = (tid & 15) * 4;

    float acc[3][2][4][4];
    #pragma unroll
    for (int w = 0; w < 3; w++)
        #pragma unroll
        for (int am = 0; am < 2; am++)
            #pragma unroll
            for (int an = 0; an < 4; an++)
                #pragma unroll
                for (int e = 0; e < 4; e++) acc[w][am][an][e] = 0.f;

    auto load_panel = [&](int stage, int k0) {
        uint32_t xs = smem_base + (stage * X_TILE_U32) * 4;
        #pragma unroll
        for (int i = 0; i < 4; i++) {
            cp16(xs + (xrow[i] * XS_STRIDE + xcol4) * 4,
                 X + (size_t)(m0 + xrow[i]) * DD + k0 + xcol4);
        }
        #pragma unroll
        for (int w = 0; w < 3; w++) {
            uint32_t bs = smem_base + (2 * X_TILE_U32 + (stage * 3 + w) * B_TILE_U32) * 4;
            #pragma unroll
            for (int i = 0; i < 2; i++) {
                cp16(bs + (brow[i] * BS_STRIDE + bcol4) * 4,
                     Ws[w] + (size_t)(k0 + brow[i]) * DD + n0 + bcol4);
            }
        }
    };

    uint32_t (*Xsv)[XS_STRIDE] = (uint32_t(*)[XS_STRIDE])smbuf;
    uint32_t (*Bsv)[BS_STRIDE] = (uint32_t(*)[BS_STRIDE])(smbuf + 2 * X_TILE_U32);

    load_panel(0, 0);
    CP_COMMIT();

    const int NP = DD / 32;
    for (int kt = 0; kt < NP; kt++) {
        if (kt + 1 < NP) {
            load_panel((kt + 1) & 1, (kt + 1) * 32);
            CP_COMMIT();
            CP_WAIT(1);
        } else {
            CP_WAIT(0);
        }
        __syncthreads();

        const int st = kt & 1;
        uint32_t (*Xs)[XS_STRIDE] = Xsv + st * 128;
        #pragma unroll
        for (int ks = 0; ks < 32; ks += 8) {
            uint32_t a[2][4];
            #pragma unroll
            for (int am = 0; am < 2; am++) {
                int row = wm * 32 + am * 16;
                a[am][0] = Xs[row + g][ks + t];
                a[am][1] = Xs[row + 8 + g][ks + t];
                a[am][2] = Xs[row + g][ks + t + 4];
                a[am][3] = Xs[row + 8 + g][ks + t + 4];
            }
            #pragma unroll
            for (int w = 0; w < 3; w++) {
                uint32_t (*Bs)[BS_STRIDE] = Bsv + (st * 3 + w) * 32;
                #pragma unroll
                for (int an = 0; an < 4; an++) {
                    int n = wn * 32 + an * 8 + g;
                    uint32_t b0 = Bs[ks + t][n];
                    uint32_t b1 = Bs[ks + t + 4][n];
                    mma_tf32(acc[w][0][an], a[0][0], a[0][1], a[0][2], a[0][3], b0, b1);
                    mma_tf32(acc[w][1][an], a[1][0], a[1][1], a[1][2], a[1][3], b0, b1);
                }
            }
        }
        __syncthreads();
    }

    int mb[2][2], mn[2][2];
    #pragma unroll
    for (int am = 0; am < 2; am++)
        #pragma unroll
        for (int hl = 0; hl < 2; hl++) {
            int m = m0 + wm * 32 + am * 16 + g + hl * 8;
            mb[am][hl] = m / NN;
            mn[am][hl] = m % NN;
        }

    const float* biases[3] = {bq, bk, bv};
    #pragma unroll
    for (int w = 0; w < 3; w++) {
        float* out = (w == 0) ? g_q : (w == 1) ? g_k : g_v;
        const float* bias = biases[w];
        float scl = (w == 0) ? 0.125f : 1.0f;
        #pragma unroll
        for (int an = 0; an < 4; an++) {
            int col = n0 + wn * 32 + an * 8 + 2 * t;
            #pragma unroll
            for (int cc = 0; cc < 2; cc++) {
                int e = col + cc;
                int h = e >> 6, dh = e & 63;
                float bv_ = bias[e];
                #pragma unroll
                for (int am = 0; am < 2; am++)
                    #pragma unroll
                    for (int hl = 0; hl < 2; hl++) {
                        float val = (acc[w][am][an][hl * 2 + cc] + bv_) * scl;
                        out[((size_t)(h * BB + mb[am][hl]) * NN + mn[am][hl]) * DHE + dh]
                            = __uint_as_float(f2tf(val));
                    }
            }
        }
    }
}

// ============================================================
// K3: flash attention with sliding-window relative-position bias.
// R chunk c = q · pos[base0+64c-63 .. base0+64c]^T; per j-tile reuse
// chunk(jt) + chunk(jt+1); compute chunk(jt+2) in the same pass.
// 128 threads (4 warps x 16 rows). smem: 6 x 64x68 u32 = 104448 B.
// ============================================================
__global__ __launch_bounds__(128) void flash_kernel(const float* __restrict__ pos_k,
                                                    const int* __restrict__ vl)
{
    extern __shared__ uint32_t fsm[];
    uint32_t (*qs)[68] = (uint32_t(*)[68])fsm;
    uint32_t (*ks)[68] = (uint32_t(*)[68])(fsm + 4352);
    uint32_t (*vs)[68] = (uint32_t(*)[68])(fsm + 2 * 4352);
    uint32_t (*pp)[68] = (uint32_t(*)[68])(fsm + 3 * 4352);   // pos chunk, then P
    float (*Xf0)[68] = (float(*)[68])(fsm + 4 * 4352);        // R ping
    float (*Xf1)[68] = (float(*)[68])(fsm + 5 * 4352);        // R pong

    const int x = blockIdx.y;
    const int b = x & (BB - 1);
    const int vlen = vl[b];
    const int i0 = blockIdx.x * 64;
    const int base0 = PCLIP - i0;    // rel at (j=0, i=i0)

    const int tid = threadIdx.x;
    const int lane = tid & 31, warp = tid >> 5;
    const int g = lane >> 2, t = lane & 3;
    const int ib = warp * 16;

    const float* qb = g_q + (size_t)x * NN * DHE;
    const float* kb = g_k + (size_t)x * NN * DHE;
    const float* vb = g_v + (size_t)x * NN * DHE;

    // load q tile once (tf32 bits)
    #pragma unroll
    for (int it = 0; it < 8; it++) {
        int idx = tid + it * 128;
        int r = idx >> 4, c4 = (idx & 15) * 4;
        uint4 val = make_uint4(0u, 0u, 0u, 0u);
        if (i0 + r < NN) val = *(const uint4*)(qb + (size_t)(i0 + r) * DHE + c4);
        qs[r][c4] = val.x; qs[r][c4 + 1] = val.y; qs[r][c4 + 2] = val.z; qs[r][c4 + 3] = val.w;
    }

    const int irow0 = i0 + ib + g;
    const int irow1 = irow0 + 8;
    const bool iok0 = irow0 < NN, iok1 = irow1 < NN;
    const int ii0 = ib + g, ii1 = ib + g + 8;

    // pos chunk loader: chunk c row r -> rel = base0 + 64c - 63 + r
    auto load_pos = [&](int c) {
        #pragma unroll
        for (int it = 0; it < 8; it++) {
            int idx = tid + it * 128;
            int r = idx >> 4, c4 = (idx & 15) * 4;
            int rel = base0 + 64 * c - 63 + r;
            uint4 pv = make_uint4(0u, 0u, 0u, 0u);
            if (rel >= 0 && rel < RLEN)
                pv = *(const uint4*)(pos_k + (size_t)rel * DHE + c4);
            pp[r][c4] = pv.x; pp[r][c4 + 1] = pv.y; pp[r][c4 + 2] = pv.z; pp[r][c4 + 3] = pv.w;
        }
    };

    // R chunk mma (reads qs + pp) into tacc
    auto r_mma = [&](float tacc[8][4]) {
        #pragma unroll
        for (int fn = 0; fn < 8; fn++)
            #pragma unroll
            for (int e = 0; e < 4; e++) tacc[fn][e] = 0.f;
        #pragma unroll
        for (int kk = 0; kk < 64; kk += 8) {
            uint32_t a0 = qs[ib + g][kk + t];
            uint32_t a1 = qs[ib + 8 + g][kk + t];
            uint32_t a2 = qs[ib + g][kk + t + 4];
            uint32_t a3 = qs[ib + 8 + g][kk + t + 4];
            #pragma unroll
            for (int fn = 0; fn < 8; fn++) {
                int n = fn * 8 + g;
                mma_tf32(tacc[fn], a0, a1, a2, a3, pp[n][kk + t], pp[n][kk + t + 4]);
            }
        }
    };

    auto r_store = [&](float (*Xf)[68], const float tacc[8][4]) {
        #pragma unroll
        for (int fn = 0; fn < 8; fn++) {
            int c0 = fn * 8 + 2 * t;
            Xf[ii0][c0]     = tacc[fn][0]; Xf[ii0][c0 + 1] = tacc[fn][1];
            Xf[ii1][c0]     = tacc[fn][2]; Xf[ii1][c0 + 1] = tacc[fn][3];
        }
    };

    // ---- prologue: chunks 0 and 1 ----
    float tacc[8][4];
    __syncthreads();              // qs visible before first mma... (written by all)
    load_pos(0);
    __syncthreads();
    r_mma(tacc);
    r_store(Xf0, tacc);
    __syncthreads();              // all warps done reading pp before reload
    load_pos(1);
    __syncthreads();
    r_mma(tacc);
    r_store(Xf1, tacc);
    __syncwarp();

    float m0 = -1e30f, m1 = -1e30f, l0 = 0.f, l1 = 0.f;
    float oacc[8][4];
    #pragma unroll
    for (int fn = 0; fn < 8; fn++)
        #pragma unroll
        for (int e = 0; e < 4; e++) oacc[fn][e] = 0.f;

    int p = 0;
    for (int jt = 0; 64 * jt < vlen; jt++) {
        const int j0 = 64 * jt;
        __syncthreads();          // prev iter done with ks/vs/pp
        // load k/v tiles and pos chunk jt+2
        #pragma unroll
        for (int it = 0; it < 8; it++) {
            int idx = tid + it * 128;
            int r = idx >> 4, c4 = (idx & 15) * 4;
            uint4 kv = make_uint4(0u, 0u, 0u, 0u), vv = make_uint4(0u, 0u, 0u, 0u);
            if (j0 + r < NN) {
                kv = *(const uint4*)(kb + (size_t)(j0 + r) * DHE + c4);
                vv = *(const uint4*)(vb + (size_t)(j0 + r) * DHE + c4);
            }
            ks[r][c4] = kv.x; ks[r][c4 + 1] = kv.y; ks[r][c4 + 2] = kv.z; ks[r][c4 + 3] = kv.w;
            vs[r][c4] = vv.x; vs[r][c4 + 1] = vv.y; vs[r][c4 + 2] = vv.z; vs[r][c4 + 3] = vv.w;
            int rel = base0 + 64 * (jt + 2) - 63 + r;
            uint4 pv = make_uint4(0u, 0u, 0u, 0u);
            if (rel >= 0 && rel < RLEN)
                pv = *(const uint4*)(pos_k + (size_t)rel * DHE + c4);
            pp[r][c4] = pv.x; pp[r][c4 + 1] = pv.y; pp[r][c4 + 2] = pv.z; pp[r][c4 + 3] = pv.w;
        }
        __syncthreads();

        // ---- Rnew = chunk(jt+2) (reads pp) ----
        r_mma(tacc);

        // ---- S = q · k^T ----
        float sacc[8][4];
        #pragma unroll
        for (int fn = 0; fn < 8; fn++)
            #pragma unroll
            for (int e = 0; e < 4; e++) sacc[fn][e] = 0.f;
        #pragma unroll
        for (int kk = 0; kk < 64; kk += 8) {
            uint32_t a0 = qs[ib + g][kk + t];
            uint32_t a1 = qs[ib + 8 + g][kk + t];
            uint32_t a2 = qs[ib + g][kk + t + 4];
            uint32_t a3 = qs[ib + 8 + g][kk + t + 4];
            #pragma unroll
            for (int fn = 0; fn < 8; fn++) {
                int n = fn * 8 + g;
                mma_tf32(sacc[fn], a0, a1, a2, a3, ks[n][kk + t], ks[n][kk + t + 4]);
            }
        }
        __syncthreads();          // all warps done reading pp (Rnew) before P write

        // ---- gather bias from A=X[p] (d<=0), B=X[p^1] (d>0); mask; max ----
        float (*Af)[68] = p ? Xf1 : Xf0;
        float (*Bf)[68] = p ? Xf0 : Xf1;
        float tm0 = -1e30f, tm1 = -1e30f;
        #pragma unroll
        for (int fn = 0; fn < 8; fn++) {
            int jj = fn * 8 + 2 * t;
            int j = j0 + jj;
            int d00 = jj - ii0;
            int d10 = jj - ii1;
            float r00 = (d00 > 0)     ? Bf[ii0][d00 - 1] : Af[ii0][d00 + 63];
            float r01 = (d00 + 1 > 0) ? Bf[ii0][d00]     : Af[ii0][d00 + 64];
            float r10 = (d10 > 0)     ? Bf[ii1][d10 - 1] : Af[ii1][d10 + 63];
            float r11 = (d10 + 1 > 0) ? Bf[ii1][d10]     : Af[ii1][d10 + 64];
            sacc[fn][0] = (j < vlen)     ? sacc[fn][0] + r00 : -1e30f;
            sacc[fn][1] = (j + 1 < vlen) ? sacc[fn][1] + r01 : -1e30f;
            sacc[fn][2] = (j < vlen)     ? sacc[fn][2] + r10 : -1e30f;
            sacc[fn][3] = (j + 1 < vlen) ? sacc[fn][3] + r11 : -1e30f;
            tm0 = fmaxf(tm0, fmaxf(sacc[fn][0], sacc[fn][1]));
            tm1 = fmaxf(tm1, fmaxf(sacc[fn][2], sacc[fn][3]));
        }
        tm0 = fmaxf(tm0, __shfl_xor_sync(0xffffffffu, tm0, 1));
        tm0 = fmaxf(tm0, __shfl_xor_sync(0xffffffffu, tm0, 2));
        tm1 = fmaxf(tm1, __shfl_xor_sync(0xffffffffu, tm1, 1));
        tm1 = fmaxf(tm1, __shfl_xor_sync(0xffffffffu, tm1, 2));

        float mn0 = fmaxf(m0, tm0), mn1 = fmaxf(m1, tm1);
        float sc0 = __expf(m0 - mn0), sc1 = __expf(m1 - mn1);
        m0 = mn0; m1 = mn1;

        // ---- exp, stage P into pp (tf32), row sums ----
        float tl0 = 0.f, tl1 = 0.f;
        #pragma unroll
        for (int fn = 0; fn < 8; fn++) {
            float p00 = __expf(sacc[fn][0] - mn0);
            float p01 = __expf(sacc[fn][1] - mn0);
            float p10 = __expf(sacc[fn][2] - mn1);
            float p11 = __expf(sacc[fn][3] - mn1);
            tl0 += p00 + p01; tl1 += p10 + p11;
            int c0 = fn * 8 + 2 * t;
            pp[ii0][c0]     = f2tf(p00);
            pp[ii0][c0 + 1] = f2tf(p01);
            pp[ii1][c0]     = f2tf(p10);
            pp[ii1][c0 + 1] = f2tf(p11);
        }
        tl0 += __shfl_xor_sync(0xffffffffu, tl0, 1);
        tl0 += __shfl_xor_sync(0xffffffffu, tl0, 2);
        tl1 += __shfl_xor_sync(0xffffffffu, tl1, 1);
        tl1 += __shfl_xor_sync(0xffffffffu, tl1, 2);
        l0 = l0 * sc0 + tl0;
        l1 = l1 * sc1 + tl1;

        #pragma unroll
        for (int fn = 0; fn < 8; fn++) {
            oacc[fn][0] *= sc0; oacc[fn][1] *= sc0;
            oacc[fn][2] *= sc1; oacc[fn][3] *= sc1;
        }

        __syncwarp();             // gather reads of A done; P visible within warp

        // retire A chunk: write Rnew (chunk jt+2) into X[p]
        r_store(Af, tacc);
        p ^= 1;

        // ---- O += P · V ----
        #pragma unroll
        for (int kk = 0; kk < 64; kk += 8) {
            uint32_t a0 = pp[ib + g][kk + t];
            uint32_t a1 = pp[ib + 8 + g][kk + t];
            uint32_t a2 = pp[ib + g][kk + t + 4];
            uint32_t a3 = pp[ib + 8 + g][kk + t + 4];
            #pragma unroll
            for (int fn = 0; fn < 8; fn++) {
                int n = fn * 8 + g;
                mma_tf32(oacc[fn], a0, a1, a2, a3, vs[kk + t][n], vs[kk + t + 4][n]);
            }
        }
        __syncwarp();
    }

    float inv0 = 1.f / l0, inv1 = 1.f / l1;
    float* ob = g_ao + (size_t)x * NN * DHE;
    #pragma unroll
    for (int fn = 0; fn < 8; fn++) {
        int dh = fn * 8 + 2 * t;
        if (iok0) {
            float2 v;
            v.x = __uint_as_float(f2tf(oacc[fn][0] * inv0));
            v.y = __uint_as_float(f2tf(oacc[fn][1] * inv0));
            *(float2*)(ob + (size_t)irow0 * DHE + dh) = v;
        }
        if (iok1) {
            float2 v;
            v.x = __uint_as_float(f2tf(oacc[fn][2] * inv1));
            v.y = __uint_as_float(f2tf(oacc[fn][3] * inv1));
            *(float2*)(ob + (size_t)irow1 * DHE + dh) = v;
        }
    }
}

// ============================================================
// K5: output projection, cp.async 2-stage pipeline, block tile 128x128.
// ============================================================
__global__ __launch_bounds__(256) void outproj_gemm(const float* __restrict__ W,
                                                    const float* __restrict__ bias,
                                                    const float* __restrict__ query)
{
    extern __shared__ uint32_t smbuf[];
    const uint32_t smem_base = (uint32_t)__cvta_generic_to_shared(smbuf);

    const int tid = threadIdx.x;
    const int lane = tid & 31, warp = tid >> 5;
    const int g = lane >> 2, t = lane & 3;
    const int wm = warp >> 1, wn = warp & 1;
    const int m0 = blockIdx.x * 128;
    const int n0 = blockIdx.y * 128;

    const int xrow[4] = { (tid) >> 3, (tid + 256) >> 3, (tid + 512) >> 3, (tid + 768) >> 3 };
    const int xcol4 = (tid & 7) * 4;
    const int brow[4] = { tid >> 5, (tid + 256) >> 5, (tid + 512) >> 5, (tid + 768) >> 5 };
    const int bcol4 = (tid & 31) * 4;

    size_t pre[4];
    #pragma unroll
    for (int i = 0; i < 4; i++) {
        int m = m0 + xrow[i];
        int bb = m / NN, nn = m % NN;
        pre[i] = ((size_t)bb * NN + nn) * DHE;
    }

    float acc[2][8][4];
    #pragma unroll
    for (int am = 0; am < 2; am++)
        #pragma unroll
        for (int an = 0; an < 8; an++)
            #pragma unroll
            for (int e = 0; e < 4; e++) acc[am][an][e] = 0.f;

    auto load_panel = [&](int stage, int kt) {
        const int h = kt >> 1;
        const int dh0 = (kt & 1) * 32;
        const size_t hoff = (size_t)h * BB * NN * DHE;
        uint32_t xs = smem_base + (stage * X_TILE_U32) * 4;
        #pragma unroll
        for (int i = 0; i < 4; i++) {
            cp16(xs + (xrow[i] * XS_STRIDE + xcol4) * 4,
                 g_ao + hoff + pre[i] + dh0 + xcol4);
        }
        uint32_t bs = smem_base + (2 * X_TILE_U32 + stage * OB_TILE_U32) * 4;
        #pragma unroll
        for (int i = 0; i < 4; i++) {
            cp16(bs + (brow[i] * OBS_STRIDE + bcol4) * 4,
                 W + (size_t)(kt * 32 + brow[i]) * DD + n0 + bcol4);
        }
    };

    uint32_t (*Xsv)[XS_STRIDE] = (uint32_t(*)[XS_STRIDE])smbuf;
    uint32_t (*Bsv)[OBS_STRIDE] = (uint32_t(*)[OBS_STRIDE])(smbuf + 2 * X_TILE_U32);

    load_panel(0, 0);
    CP_COMMIT();

    const int NP = DD / 32;
    for (int kt = 0; kt < NP; kt++) {
        if (kt + 1 < NP) {
            load_panel((kt + 1) & 1, kt + 1);
            CP_COMMIT();
            CP_WAIT(1);
        } else {
            CP_WAIT(0);
        }
        __syncthreads();

        const int st = kt & 1;
        uint32_t (*Xs)[XS_STRIDE] = Xsv + st * 128;
        uint32_t (*Bs)[OBS_STRIDE] = Bsv + st * 32;
        #pragma unroll
        for (int ks = 0; ks < 32; ks += 8) {
            uint32_t a[2][4];
            #pragma unroll
            for (int am = 0; am < 2; am++) {
                int row = wm * 32 + am * 16;
                a[am][0] = Xs[row + g][ks + t];
                a[am][1] = Xs[row + 8 + g][ks + t];
                a[am][2] = Xs[row + g][ks + t + 4];
                a[am][3] = Xs[row + 8 + g][ks + t + 4];
            }
            #pragma unroll
            for (int an = 0; an < 8; an++) {
                int n = wn * 64 + an * 8 + g;
                uint32_t b0 = Bs[ks + t][n];
                uint32_t b1 = Bs[ks + t + 4][n];
                mma_tf32(acc[0][an], a[0][0], a[0][1], a[0][2], a[0][3], b0, b1);
                mma_tf32(acc[1][an], a[1][0], a[1][1], a[1][2], a[1][3], b0, b1);
            }
        }
        __syncthreads();
    }

    #pragma unroll
    for (int an = 0; an < 8; an++) {
        int col = n0 + wn * 64 + an * 8 + 2 * t;
        #pragma unroll
        for (int cc = 0; cc < 2; cc++) {
            int e = col + cc;
            float bv_ = bias[e];
            #pragma unroll
            for (int am = 0; am < 2; am++)
                #pragma unroll
                for (int hl = 0; hl < 2; hl++) {
                    int m = m0 + wm * 32 + am * 16 + g + hl * 8;
                    g_o[(size_t)m * DD + e] =
                        acc[am][an][hl * 2 + cc] + bv_ + query[(size_t)m * DD + e];
                }
        }
    }
}

// ============================================================
// K6: LayerNorm over D=512 per row -> d_out
// ============================================================
__global__ __launch_bounds__(256) void ln_kernel(const float* __restrict__ gamma,
                                                 const float* __restrict__ beta,
                                                 float* __restrict__ out)
{
    const int m = blockIdx.x;
    const float* xr = g_o + (size_t)m * DD;
    const int tid = threadIdx.x;

    __shared__ float red[8];

    float x0 = xr[tid], x1 = xr[tid + 256];
    float s = x0 + x1;
    #pragma unroll
    for (int off = 16; off > 0; off >>= 1)
        s += __shfl_xor_sync(0xffffffff, s, off);
    if ((tid & 31) == 0) red[tid >> 5] = s;
    __syncthreads();
    float tot = 0.f;
    #pragma unroll
    for (int w = 0; w < 8; w++) tot += red[w];
    float mean = tot * (1.f / DD);

    float d0 = x0 - mean, d1 = x1 - mean;
    float ss = d0 * d0 + d1 * d1;
    #pragma unroll
    for (int off = 16; off > 0; off >>= 1)
        ss += __shfl_xor_sync(0xffffffff, ss, off);
    __syncthreads();
    if ((tid & 31) == 0) red[tid >> 5] = ss;
    __syncthreads();
    float tss = 0.f;
    #pragma unroll
    for (int w = 0; w < 8; w++) tss += red[w];
    float var = tss * (1.f / DD);
    float rstd = rsqrtf(var + 1e-7f);

    out[(size_t)m * DD + tid]       = gamma[tid]       * d0 * rstd + beta[tid];
    out[(size_t)m * DD + tid + 256] = gamma[tid + 256] * d1 * rstd + beta[tid + 256];
}

// ============================================================
extern "C" void kernel_launch(void* const* d_in, const int* in_sizes, int n_in,
                              void* d_out, int out_size)
{
    const float* query = (const float*)d_in[0];
    const float* Wq    = (const float*)d_in[1];
    const float* bq    = (const float*)d_in[2];
    const float* Wk    = (const float*)d_in[3];
    const float* bk    = (const float*)d_in[4];
    const float* Wv    = (const float*)d_in[5];
    const float* bv    = (const float*)d_in[6];
    const float* Wh    = (const float*)d_in[7];
    const float* bh    = (const float*)d_in[8];
    const float* pos_k = (const float*)d_in[9];
    const float* gamma = (const float*)d_in[10];
    const float* beta  = (const float*)d_in[11];
    const int*   vl    = (const int*)d_in[12];
    float* out = (float*)d_out;

    const int FLASH_SMEM = 6 * 64 * 68 * 4;                         // 104448 B
    const int QKV_SMEM   = (2 * X_TILE_U32 + 6 * B_TILE_U32) * 4;   // 89088 B
    const int OUT_SMEM   = (2 * X_TILE_U32 + 2 * OB_TILE_U32) * 4;  // 70656 B

    static int smem_set = 0;
    if (!smem_set) {
        cudaFuncSetAttribute(flash_kernel,
                             cudaFuncAttributeMaxDynamicSharedMemorySize, FLASH_SMEM);
        cudaFuncSetAttribute(qkv_fused,
                             cudaFuncAttributeMaxDynamicSharedMemorySize, QKV_SMEM);
        cudaFuncSetAttribute(outproj_gemm,
                             cudaFuncAttributeMaxDynamicSharedMemorySize, OUT_SMEM);
        smem_set = 1;
    }

    qkv_fused<<<dim3(BN / 128, DD / 64), 256, QKV_SMEM>>>(query, Wq, bq, Wk, bk, Wv, bv);

    flash_kernel<<<dim3(9, HB), 128, FLASH_SMEM>>>(pos_k, vl);

    outproj_gemm<<<dim3(BN / 128, DD / 128), 256, OUT_SMEM>>>(Wh, bh, query);
    ln_kernel<<<BN, 256>>>(gamma, beta, out);
}

// round 7
// speedup vs baseline: 4.8640x; 1.0250x over previous
#include <cuda_runtime.h>
#include <cstdint>
#include <math.h>

#define BB 32
#define NN 540
#define DD 512
#define HH 8
#define DHE 64
#define HB (HH*BB)          // 256
#define BN (BB*NN)          // 17280
#define PCLIP 539
#define RLEN (2*PCLIP+1)    // 1079

// -------- scratch (device globals) --------
__device__ float g_q[(size_t)HB*NN*DHE];   // tf32 bits, q pre-scaled by 0.125
__device__ float g_k[(size_t)HB*NN*DHE];   // tf32 bits
__device__ float g_v[(size_t)HB*NN*DHE];   // tf32 bits
__device__ float g_ao[(size_t)HB*NN*DHE];  // attn@v, tf32 bits, head-major
__device__ float g_o[(size_t)BN*DD];       // pre-LN (fp32)

// -------- helpers --------
__device__ __forceinline__ uint32_t f2tf(float f) {
    uint32_t u;
    asm("cvt.rna.tf32.f32 %0, %1;" : "=r"(u) : "f"(f));
    return u;
}

__device__ __forceinline__ void mma_tf32(float c[4],
                                         uint32_t a0, uint32_t a1, uint32_t a2, uint32_t a3,
                                         uint32_t b0, uint32_t b1) {
    asm volatile(
        "mma.sync.aligned.m16n8k8.row.col.f32.tf32.tf32.f32 "
        "{%0,%1,%2,%3}, {%4,%5,%6,%7}, {%8,%9}, {%0,%1,%2,%3};\n"
        : "+f"(c[0]), "+f"(c[1]), "+f"(c[2]), "+f"(c[3])
        : "r"(a0), "r"(a1), "r"(a2), "r"(a3), "r"(b0), "r"(b1));
}

__device__ __forceinline__ void cp16(uint32_t smem_u32_addr, const void* gptr) {
    asm volatile("cp.async.cg.shared.global [%0], [%1], 16;\n"
                 :: "r"(smem_u32_addr), "l"(gptr));
}
#define CP_COMMIT() asm volatile("cp.async.commit_group;\n" ::)
#define CP_WAIT(n)  asm volatile("cp.async.wait_group %0;\n" :: "n"(n))

// smem tiling constants for pipelined GEMMs
#define XS_STRIDE 36
#define X_TILE_U32 (128*XS_STRIDE)     // 4608
#define BS_STRIDE 68
#define B_TILE_U32 (32*BS_STRIDE)      // 2176
#define OBS_STRIDE 132
#define OB_TILE_U32 (32*OBS_STRIDE)    // 4224

// ============================================================
// K1: fused QKV projection, tf32 mma, cp.async 2-stage pipeline.
// ============================================================
__global__ __launch_bounds__(256) void qkv_fused(const float* __restrict__ X,
                                                 const float* __restrict__ Wq, const float* __restrict__ bq,
                                                 const float* __restrict__ Wk, const float* __restrict__ bk,
                                                 const float* __restrict__ Wv, const float* __restrict__ bv)
{
    extern __shared__ uint32_t smbuf[];
    const uint32_t smem_base = (uint32_t)__cvta_generic_to_shared(smbuf);

    const int tid = threadIdx.x;
    const int lane = tid & 31, warp = tid >> 5;
    const int g = lane >> 2, t = lane & 3;
    const int wm = warp >> 1, wn = warp & 1;
    const int m0 = blockIdx.x * 128;
    const int n0 = blockIdx.y * 64;

    const float* Ws[3] = {Wq, Wk, Wv};

    const int xrow[4] = { (tid) >> 3, (tid + 256) >> 3, (tid + 512) >> 3, (tid + 768) >> 3 };
    const int xcol4 = (tid & 7) * 4;
    const int brow[2] = { tid >> 4, (tid + 256) >> 4 };
    const int bcol4 = (tid & 15) * 4;

    float acc[3][2][4][4];
    #pragma unroll
    for (int w = 0; w < 3; w++)
        #pragma unroll
        for (int am = 0; am < 2; am++)
            #pragma unroll
            for (int an = 0; an < 4; an++)
                #pragma unroll
                for (int e = 0; e < 4; e++) acc[w][am][an][e] = 0.f;

    auto load_panel = [&](int stage, int k0) {
        uint32_t xs = smem_base + (stage * X_TILE_U32) * 4;
        #pragma unroll
        for (int i = 0; i < 4; i++) {
            cp16(xs + (xrow[i] * XS_STRIDE + xcol4) * 4,
                 X + (size_t)(m0 + xrow[i]) * DD + k0 + xcol4);
        }
        #pragma unroll
        for (int w = 0; w < 3; w++) {
            uint32_t bs = smem_base + (2 * X_TILE_U32 + (stage * 3 + w) * B_TILE_U32) * 4;
            #pragma unroll
            for (int i = 0; i < 2; i++) {
                cp16(bs + (brow[i] * BS_STRIDE + bcol4) * 4,
                     Ws[w] + (size_t)(k0 + brow[i]) * DD + n0 + bcol4);
            }
        }
    };

    uint32_t (*Xsv)[XS_STRIDE] = (uint32_t(*)[XS_STRIDE])smbuf;
    uint32_t (*Bsv)[BS_STRIDE] = (uint32_t(*)[BS_STRIDE])(smbuf + 2 * X_TILE_U32);

    load_panel(0, 0);
    CP_COMMIT();

    const int NP = DD / 32;
    for (int kt = 0; kt < NP; kt++) {
        if (kt + 1 < NP) {
            load_panel((kt + 1) & 1, (kt + 1) * 32);
            CP_COMMIT();
            CP_WAIT(1);
        } else {
            CP_WAIT(0);
        }
        __syncthreads();

        const int st = kt & 1;
        uint32_t (*Xs)[XS_STRIDE] = Xsv + st * 128;
        #pragma unroll
        for (int ks = 0; ks < 32; ks += 8) {
            uint32_t a[2][4];
            #pragma unroll
            for (int am = 0; am < 2; am++) {
                int row = wm * 32 + am * 16;
                a[am][0] = Xs[row + g][ks + t];
                a[am][1] = Xs[row + 8 + g][ks + t];
                a[am][2] = Xs[row + g][ks + t + 4];
                a[am][3] = Xs[row + 8 + g][ks + t + 4];
            }
            #pragma unroll
            for (int w = 0; w < 3; w++) {
                uint32_t (*Bs)[BS_STRIDE] = Bsv + (st * 3 + w) * 32;
                #pragma unroll
                for (int an = 0; an < 4; an++) {
                    int n = wn * 32 + an * 8 + g;
                    uint32_t b0 = Bs[ks + t][n];
                    uint32_t b1 = Bs[ks + t + 4][n];
                    mma_tf32(acc[w][0][an], a[0][0], a[0][1], a[0][2], a[0][3], b0, b1);
                    mma_tf32(acc[w][1][an], a[1][0], a[1][1], a[1][2], a[1][3], b0, b1);
                }
            }
        }
        __syncthreads();
    }

    int mb[2][2], mn[2][2];
    #pragma unroll
    for (int am = 0; am < 2; am++)
        #pragma unroll
        for (int hl = 0; hl < 2; hl++) {
            int m = m0 + wm * 32 + am * 16 + g + hl * 8;
            mb[am][hl] = m / NN;
            mn[am][hl] = m % NN;
        }

    const float* biases[3] = {bq, bk, bv};
    #pragma unroll
    for (int w = 0; w < 3; w++) {
        float* out = (w == 0) ? g_q : (w == 1) ? g_k : g_v;
        const float* bias = biases[w];
        float scl = (w == 0) ? 0.125f : 1.0f;
        #pragma unroll
        for (int an = 0; an < 4; an++) {
            int col = n0 + wn * 32 + an * 8 + 2 * t;
            #pragma unroll
            for (int cc = 0; cc < 2; cc++) {
                int e = col + cc;
                int h = e >> 6, dh = e & 63;
                float bv_ = bias[e];
                #pragma unroll
                for (int am = 0; am < 2; am++)
                    #pragma unroll
                    for (int hl = 0; hl < 2; hl++) {
                        float val = (acc[w][am][an][hl * 2 + cc] + bv_) * scl;
                        out[((size_t)(h * BB + mb[am][hl]) * NN + mn[am][hl]) * DHE + dh]
                            = __uint_as_float(f2tf(val));
                    }
            }
        }
    }
}

// ============================================================
// K3: flash attention, sliding-window R chunks + cp.async pipelined
// k/v/pos loads (split commit groups; k prefetched a full iter ahead).
// 128 threads (4 warps x 16 rows). smem: 6 x 64x68 u32 = 104448 B.
// ============================================================
__global__ __launch_bounds__(128) void flash_kernel(const float* __restrict__ pos_k,
                                                    const int* __restrict__ vl)
{
    extern __shared__ uint32_t fsm[];
    uint32_t (*qs)[68] = (uint32_t(*)[68])fsm;
    uint32_t (*ks)[68] = (uint32_t(*)[68])(fsm + 4352);
    uint32_t (*vs)[68] = (uint32_t(*)[68])(fsm + 2 * 4352);
    uint32_t (*pp)[68] = (uint32_t(*)[68])(fsm + 3 * 4352);   // pos chunk, then P
    float (*Xf0)[68] = (float(*)[68])(fsm + 4 * 4352);        // R ping
    float (*Xf1)[68] = (float(*)[68])(fsm + 5 * 4352);        // R pong

    const uint32_t smem_base = (uint32_t)__cvta_generic_to_shared(fsm);
    const uint32_t ks_base = smem_base + 4352 * 4;
    const uint32_t vs_base = smem_base + 2 * 4352 * 4;
    const uint32_t pp_base = smem_base + 3 * 4352 * 4;

    const int x = blockIdx.y;
    const int b = x & (BB - 1);
    const int vlen = vl[b];
    const int i0 = blockIdx.x * 64;
    const int base0 = PCLIP - i0;    // rel at (j=0, i=i0)

    const int tid = threadIdx.x;
    const int lane = tid & 31, warp = tid >> 5;
    const int g = lane >> 2, t = lane & 3;
    const int ib = warp * 16;

    const float* qb = g_q + (size_t)x * NN * DHE;
    const float* kb = g_k + (size_t)x * NN * DHE;
    const float* vb = g_v + (size_t)x * NN * DHE;

    // per-thread staging coords: 8 chunks of (row, col4)
    const int lrow[8] = { tid >> 4, (tid + 128) >> 4, (tid + 256) >> 4, (tid + 384) >> 4,
                          (tid + 512) >> 4, (tid + 640) >> 4, (tid + 768) >> 4, (tid + 896) >> 4 };
    const int lc4 = (tid & 15) * 4;

    // load q tile once (plain LDG.128)
    #pragma unroll
    for (int it = 0; it < 8; it++) {
        int r = lrow[it];
        uint4 val = make_uint4(0u, 0u, 0u, 0u);
        if (i0 + r < NN) val = *(const uint4*)(qb + (size_t)(i0 + r) * DHE + lc4);
        qs[r][lc4] = val.x; qs[r][lc4 + 1] = val.y; qs[r][lc4 + 2] = val.z; qs[r][lc4 + 3] = val.w;
    }

    const int irow0 = i0 + ib + g;
    const int irow1 = irow0 + 8;
    const bool iok0 = irow0 < NN, iok1 = irow1 < NN;
    const int ii0 = ib + g, ii1 = ib + g + 8;

    // cp.async issuers (clamped addresses; stale/garbage rows only feed masked lanes)
    auto issue_pos = [&](int c) {
        #pragma unroll
        for (int it = 0; it < 8; it++) {
            int r = lrow[it];
            int rel = base0 + 64 * c - 63 + r;
            rel = min(max(rel, 0), RLEN - 1);
            cp16(pp_base + (r * 68 + lc4) * 4, pos_k + (size_t)rel * DHE + lc4);
        }
    };
    auto issue_k = [&](int j0) {
        #pragma unroll
        for (int it = 0; it < 8; it++) {
            int r = lrow[it];
            int row = min(j0 + r, NN - 1);
            cp16(ks_base + (r * 68 + lc4) * 4, kb + (size_t)row * DHE + lc4);
        }
    };
    auto issue_v = [&](int j0) {
        #pragma unroll
        for (int it = 0; it < 8; it++) {
            int r = lrow[it];
            int row = min(j0 + r, NN - 1);
            cp16(vs_base + (r * 68 + lc4) * 4, vb + (size_t)row * DHE + lc4);
        }
    };

    // R chunk mma (reads qs + pp) into tacc
    auto r_mma = [&](float tacc[8][4]) {
        #pragma unroll
        for (int fn = 0; fn < 8; fn++)
            #pragma unroll
            for (int e = 0; e < 4; e++) tacc[fn][e] = 0.f;
        #pragma unroll
        for (int kk = 0; kk < 64; kk += 8) {
            uint32_t a0 = qs[ib + g][kk + t];
            uint32_t a1 = qs[ib + 8 + g][kk + t];
            uint32_t a2 = qs[ib + g][kk + t + 4];
            uint32_t a3 = qs[ib + 8 + g][kk + t + 4];
            #pragma unroll
            for (int fn = 0; fn < 8; fn++) {
                int n = fn * 8 + g;
                mma_tf32(tacc[fn], a0, a1, a2, a3, pp[n][kk + t], pp[n][kk + t + 4]);
            }
        }
    };

    auto r_store = [&](float (*Xf)[68], const float tacc[8][4]) {
        #pragma unroll
        for (int fn = 0; fn < 8; fn++) {
            int c0 = fn * 8 + 2 * t;
            Xf[ii0][c0]     = tacc[fn][0]; Xf[ii0][c0 + 1] = tacc[fn][1];
            Xf[ii1][c0]     = tacc[fn][2]; Xf[ii1][c0 + 1] = tacc[fn][3];
        }
    };

    // ---- prologue: R chunks 0 and 1; leave Gk(0) in flight ----
    float tacc[8][4];
    issue_pos(0); CP_COMMIT();
    CP_WAIT(0);
    __syncthreads();              // pos0 + qs visible
    r_mma(tacc);
    r_store(Xf0, tacc);
    __syncthreads();              // all warps done reading pp
    issue_pos(1); CP_COMMIT();    // Gpos1
    issue_k(0);   CP_COMMIT();    // Gk(0)
    CP_WAIT(1);                   // pos1 done, k0 in flight
    __syncthreads();
    r_mma(tacc);
    r_store(Xf1, tacc);
    // NOTE: pp readers (all warps) drain at the first in-loop __syncthreads

    float m0 = -1e30f, m1 = -1e30f, l0 = 0.f, l1 = 0.f;
    float oacc[8][4];
    #pragma unroll
    for (int fn = 0; fn < 8; fn++)
        #pragma unroll
        for (int e = 0; e < 4; e++) oacc[fn][e] = 0.f;

    int p = 0;
    for (int jt = 0; 64 * jt < vlen; jt++) {
        const int j0 = 64 * jt;
        CP_WAIT(0);               // Gk(jt) done
        __syncthreads();          // ks visible; pp/vs free (prev readers done)
        issue_pos(jt + 2); CP_COMMIT();   // Gpos
        issue_v(j0);       CP_COMMIT();   // Gv

        // ---- S = q · k^T (ks prefetched) ----
        float sacc[8][4];
        #pragma unroll
        for (int fn = 0; fn < 8; fn++)
            #pragma unroll
            for (int e = 0; e < 4; e++) sacc[fn][e] = 0.f;
        #pragma unroll
        for (int kk = 0; kk < 64; kk += 8) {
            uint32_t a0 = qs[ib + g][kk + t];
            uint32_t a1 = qs[ib + 8 + g][kk + t];
            uint32_t a2 = qs[ib + g][kk + t + 4];
            uint32_t a3 = qs[ib + 8 + g][kk + t + 4];
            #pragma unroll
            for (int fn = 0; fn < 8; fn++) {
                int n = fn * 8 + g;
                mma_tf32(sacc[fn], a0, a1, a2, a3, ks[n][kk + t], ks[n][kk + t + 4]);
            }
        }

        CP_WAIT(1);               // Gpos done (Gv in flight)
        __syncthreads();          // pos visible; all warps done reading ks
        issue_k(j0 + 64); CP_COMMIT();    // Gk(jt+1) — full iteration to land

        // ---- Rnew = chunk(jt+2) (reads pp) ----
        r_mma(tacc);

        CP_WAIT(1);               // Gv done (Gk in flight)
        __syncthreads();          // vs visible; all warps done reading pp

        // ---- gather bias from A=X[p] (d<=0), B=X[p^1] (d>0); mask; max ----
        float (*Af)[68] = p ? Xf1 : Xf0;
        float (*Bf)[68] = p ? Xf0 : Xf1;
        float tm0 = -1e30f, tm1 = -1e30f;
        #pragma unroll
        for (int fn = 0; fn < 8; fn++) {
            int jj = fn * 8 + 2 * t;
            int j = j0 + jj;
            int d00 = jj - ii0;
            int d10 = jj - ii1;
            float r00 = (d00 > 0)     ? Bf[ii0][d00 - 1] : Af[ii0][d00 + 63];
            float r01 = (d00 + 1 > 0) ? Bf[ii0][d00]     : Af[ii0][d00 + 64];
            float r10 = (d10 > 0)     ? Bf[ii1][d10 - 1] : Af[ii1][d10 + 63];
            float r11 = (d10 + 1 > 0) ? Bf[ii1][d10]     : Af[ii1][d10 + 64];
            sacc[fn][0] = (j < vlen)     ? sacc[fn][0] + r00 : -1e30f;
            sacc[fn][1] = (j + 1 < vlen) ? sacc[fn][1] + r01 : -1e30f;
            sacc[fn][2] = (j < vlen)     ? sacc[fn][2] + r10 : -1e30f;
            sacc[fn][3] = (j + 1 < vlen) ? sacc[fn][3] + r11 : -1e30f;
            tm0 = fmaxf(tm0, fmaxf(sacc[fn][0], sacc[fn][1]));
            tm1 = fmaxf(tm1, fmaxf(sacc[fn][2], sacc[fn][3]));
        }
        tm0 = fmaxf(tm0, __shfl_xor_sync(0xffffffffu, tm0, 1));
        tm0 = fmaxf(tm0, __shfl_xor_sync(0xffffffffu, tm0, 2));
        tm1 = fmaxf(tm1, __shfl_xor_sync(0xffffffffu, tm1, 1));
        tm1 = fmaxf(tm1, __shfl_xor_sync(0xffffffffu, tm1, 2));

        float mn0 = fmaxf(m0, tm0), mn1 = fmaxf(m1, tm1);
        float sc0 = __expf(m0 - mn0), sc1 = __expf(m1 - mn1);
        m0 = mn0; m1 = mn1;

        // ---- exp, stage P into pp (tf32), row sums ----
        float tl0 = 0.f, tl1 = 0.f;
        #pragma unroll
        for (int fn = 0; fn < 8; fn++) {
            float p00 = __expf(sacc[fn][0] - mn0);
            float p01 = __expf(sacc[fn][1] - mn0);
            float p10 = __expf(sacc[fn][2] - mn1);
            float p11 = __expf(sacc[fn][3] - mn1);
            tl0 += p00 + p01; tl1 += p10 + p11;
            int c0 = fn * 8 + 2 * t;
            pp[ii0][c0]     = f2tf(p00);
            pp[ii0][c0 + 1] = f2tf(p01);
            pp[ii1][c0]     = f2tf(p10);
            pp[ii1][c0 + 1] = f2tf(p11);
        }
        tl0 += __shfl_xor_sync(0xffffffffu, tl0, 1);
        tl0 += __shfl_xor_sync(0xffffffffu, tl0, 2);
        tl1 += __shfl_xor_sync(0xffffffffu, tl1, 1);
        tl1 += __shfl_xor_sync(0xffffffffu, tl1, 2);
        l0 = l0 * sc0 + tl0;
        l1 = l1 * sc1 + tl1;

        #pragma unroll
        for (int fn = 0; fn < 8; fn++) {
            oacc[fn][0] *= sc0; oacc[fn][1] *= sc0;
            oacc[fn][2] *= sc1; oacc[fn][3] *= sc1;
        }

        __syncwarp();             // P visible within warp

        // retire A chunk: write Rnew (chunk jt+2) into X[p]
        r_store(Af, tacc);
        p ^= 1;

        // ---- O += P · V ----
        #pragma unroll
        for (int kk = 0; kk < 64; kk += 8) {
            uint32_t a0 = pp[ib + g][kk + t];
            uint32_t a1 = pp[ib + 8 + g][kk + t];
            uint32_t a2 = pp[ib + g][kk + t + 4];
            uint32_t a3 = pp[ib + 8 + g][kk + t + 4];
            #pragma unroll
            for (int fn = 0; fn < 8; fn++) {
                int n = fn * 8 + g;
                mma_tf32(oacc[fn], a0, a1, a2, a3, vs[kk + t][n], vs[kk + t + 4][n]);
            }
        }
        __syncwarp();
    }
    CP_WAIT(0);                   // drain trailing Gk

    float inv0 = 1.f / l0, inv1 = 1.f / l1;
    float* ob = g_ao + (size_t)x * NN * DHE;
    #pragma unroll
    for (int fn = 0; fn < 8; fn++) {
        int dh = fn * 8 + 2 * t;
        if (iok0) {
            float2 v;
            v.x = __uint_as_float(f2tf(oacc[fn][0] * inv0));
            v.y = __uint_as_float(f2tf(oacc[fn][1] * inv0));
            *(float2*)(ob + (size_t)irow0 * DHE + dh) = v;
        }
        if (iok1) {
            float2 v;
            v.x = __uint_as_float(f2tf(oacc[fn][2] * inv1));
            v.y = __uint_as_float(f2tf(oacc[fn][3] * inv1));
            *(float2*)(ob + (size_t)irow1 * DHE + dh) = v;
        }
    }
}

// ============================================================
// K5: output projection, cp.async 2-stage pipeline, block tile 128x128.
// ============================================================
__global__ __launch_bounds__(256) void outproj_gemm(const float* __restrict__ W,
                                                    const float* __restrict__ bias,
                                                    const float* __restrict__ query)
{
    extern __shared__ uint32_t smbuf[];
    const uint32_t smem_base = (uint32_t)__cvta_generic_to_shared(smbuf);

    const int tid = threadIdx.x;
    const int lane = tid & 31, warp = tid >> 5;
    const int g = lane >> 2, t = lane & 3;
    const int wm = warp >> 1, wn = warp & 1;
    const int m0 = blockIdx.x * 128;
    const int n0 = blockIdx.y * 128;

    const int xrow[4] = { (tid) >> 3, (tid + 256) >> 3, (tid + 512) >> 3, (tid + 768) >> 3 };
    const int xcol4 = (tid & 7) * 4;
    const int brow[4] = { tid >> 5, (tid + 256) >> 5, (tid + 512) >> 5, (tid + 768) >> 5 };
    const int bcol4 = (tid & 31) * 4;

    size_t pre[4];
    #pragma unroll
    for (int i = 0; i < 4; i++) {
        int m = m0 + xrow[i];
        int bb = m / NN, nn = m % NN;
        pre[i] = ((size_t)bb * NN + nn) * DHE;
    }

    float acc[2][8][4];
    #pragma unroll
    for (int am = 0; am < 2; am++)
        #pragma unroll
        for (int an = 0; an < 8; an++)
            #pragma unroll
            for (int e = 0; e < 4; e++) acc[am][an][e] = 0.f;

    auto load_panel = [&](int stage, int kt) {
        const int h = kt >> 1;
        const int dh0 = (kt & 1) * 32;
        const size_t hoff = (size_t)h * BB * NN * DHE;
        uint32_t xs = smem_base + (stage * X_TILE_U32) * 4;
        #pragma unroll
        for (int i = 0; i < 4; i++) {
            cp16(xs + (xrow[i] * XS_STRIDE + xcol4) * 4,
                 g_ao + hoff + pre[i] + dh0 + xcol4);
        }
        uint32_t bs = smem_base + (2 * X_TILE_U32 + stage * OB_TILE_U32) * 4;
        #pragma unroll
        for (int i = 0; i < 4; i++) {
            cp16(bs + (brow[i] * OBS_STRIDE + bcol4) * 4,
                 W + (size_t)(kt * 32 + brow[i]) * DD + n0 + bcol4);
        }
    };

    uint32_t (*Xsv)[XS_STRIDE] = (uint32_t(*)[XS_STRIDE])smbuf;
    uint32_t (*Bsv)[OBS_STRIDE] = (uint32_t(*)[OBS_STRIDE])(smbuf + 2 * X_TILE_U32);

    load_panel(0, 0);
    CP_COMMIT();

    const int NP = DD / 32;
    for (int kt = 0; kt < NP; kt++) {
        if (kt + 1 < NP) {
            load_panel((kt + 1) & 1, kt + 1);
            CP_COMMIT();
            CP_WAIT(1);
        } else {
            CP_WAIT(0);
        }
        __syncthreads();

        const int st = kt & 1;
        uint32_t (*Xs)[XS_STRIDE] = Xsv + st * 128;
        uint32_t (*Bs)[OBS_STRIDE] = Bsv + st * 32;
        #pragma unroll
        for (int ks = 0; ks < 32; ks += 8) {
            uint32_t a[2][4];
            #pragma unroll
            for (int am = 0; am < 2; am++) {
                int row = wm * 32 + am * 16;
                a[am][0] = Xs[row + g][ks + t];
                a[am][1] = Xs[row + 8 + g][ks + t];
                a[am][2] = Xs[row + g][ks + t + 4];
                a[am][3] = Xs[row + 8 + g][ks + t + 4];
            }
            #pragma unroll
            for (int an = 0; an < 8; an++) {
                int n = wn * 64 + an * 8 + g;
                uint32_t b0 = Bs[ks + t][n];
                uint32_t b1 = Bs[ks + t + 4][n];
                mma_tf32(acc[0][an], a[0][0], a[0][1], a[0][2], a[0][3], b0, b1);
                mma_tf32(acc[1][an], a[1][0], a[1][1], a[1][2], a[1][3], b0, b1);
            }
        }
        __syncthreads();
    }

    #pragma unroll
    for (int an = 0; an < 8; an++) {
        int col = n0 + wn * 64 + an * 8 + 2 * t;
        #pragma unroll
        for (int cc = 0; cc < 2; cc++) {
            int e = col + cc;
            float bv_ = bias[e];
            #pragma unroll
            for (int am = 0; am < 2; am++)
                #pragma unroll
                for (int hl = 0; hl < 2; hl++) {
                    int m = m0 + wm * 32 + am * 16 + g + hl * 8;
                    g_o[(size_t)m * DD + e] =
                        acc[am][an][hl * 2 + cc] + bv_ + query[(size_t)m * DD + e];
                }
        }
    }
}

// ============================================================
// K6: LayerNorm over D=512 per row -> d_out
// ============================================================
__global__ __launch_bounds__(256) void ln_kernel(const float* __restrict__ gamma,
                                                 const float* __restrict__ beta,
                                                 float* __restrict__ out)
{
    const int m = blockIdx.x;
    const float* xr = g_o + (size_t)m * DD;
    const int tid = threadIdx.x;

    __shared__ float red[8];

    float x0 = xr[tid], x1 = xr[tid + 256];
    float s = x0 + x1;
    #pragma unroll
    for (int off = 16; off > 0; off >>= 1)
        s += __shfl_xor_sync(0xffffffff, s, off);
    if ((tid & 31) == 0) red[tid >> 5] = s;
    __syncthreads();
    float tot = 0.f;
    #pragma unroll
    for (int w = 0; w < 8; w++) tot += red[w];
    float mean = tot * (1.f / DD);

    float d0 = x0 - mean, d1 = x1 - mean;
    float ss = d0 * d0 + d1 * d1;
    #pragma unroll
    for (int off = 16; off > 0; off >>= 1)
        ss += __shfl_xor_sync(0xffffffff, ss, off);
    __syncthreads();
    if ((tid & 31) == 0) red[tid >> 5] = ss;
    __syncthreads();
    float tss = 0.f;
    #pragma unroll
    for (int w = 0; w < 8; w++) tss += red[w];
    float var = tss * (1.f / DD);
    float rstd = rsqrtf(var + 1e-7f);

    out[(size_t)m * DD + tid]       = gamma[tid]       * d0 * rstd + beta[tid];
    out[(size_t)m * DD + tid + 256] = gamma[tid + 256] * d1 * rstd + beta[tid + 256];
}

// ============================================================
extern "C" void kernel_launch(void* const* d_in, const int* in_sizes, int n_in,
                              void* d_out, int out_size)
{
    const float* query = (const float*)d_in[0];
    const float* Wq    = (const float*)d_in[1];
    const float* bq    = (const float*)d_in[2];
    const float* Wk    = (const float*)d_in[3];
    const float* bk    = (const float*)d_in[4];
    const float* Wv    = (const float*)d_in[5];
    const float* bv    = (const float*)d_in[6];
    const float* Wh    = (const float*)d_in[7];
    const float* bh    = (const float*)d_in[8];
    const float* pos_k = (const float*)d_in[9];
    const float* gamma = (const float*)d_in[10];
    const float* beta  = (const float*)d_in[11];
    const int*   vl    = (const int*)d_in[12];
    float* out = (float*)d_out;

    const int FLASH_SMEM = 6 * 64 * 68 * 4;                         // 104448 B
    const int QKV_SMEM   = (2 * X_TILE_U32 + 6 * B_TILE_U32) * 4;   // 89088 B
    const int OUT_SMEM   = (2 * X_TILE_U32 + 2 * OB_TILE_U32) * 4;  // 70656 B

    static int smem_set = 0;
    if (!smem_set) {
        cudaFuncSetAttribute(flash_kernel,
                             cudaFuncAttributeMaxDynamicSharedMemorySize, FLASH_SMEM);
        cudaFuncSetAttribute(qkv_fused,
                             cudaFuncAttributeMaxDynamicSharedMemorySize, QKV_SMEM);
        cudaFuncSetAttribute(outproj_gemm,
                             cudaFuncAttributeMaxDynamicSharedMemorySize, OUT_SMEM);
        smem_set = 1;
    }

    qkv_fused<<<dim3(BN / 128, DD / 64), 256, QKV_SMEM>>>(query, Wq, bq, Wk, bk, Wv, bv);

    flash_kernel<<<dim3(9, HB), 128, FLASH_SMEM>>>(pos_k, vl);

    outproj_gemm<<<dim3(BN / 128, DD / 128), 256, OUT_SMEM>>>(Wh, bh, query);
    ln_kernel<<<BN, 256>>>(gamma, beta, out);
}